// round 1
// baseline (speedup 1.0000x reference)
#include <cuda_runtime.h>

// ============================================================================
// MultiHeadAttention: B=8, T=1024, D=1024, H=16, hd=64, fp32.
//   q = (x@Wq^T + bq)*s ; k = (x@Wk^T)*s ; v = x@Wv^T + bv   (s = 64^-0.25)
//   att[b,t,h*64+d] = softmax_causal(q_h @ k_h^T) @ v_h
//   out = att@Wo^T + bo
// Causal mask (-1e9 above diag) == hard causal: exp(-1e9+s) == 0 in fp32.
// ============================================================================

namespace {
constexpr int Bz = 8, Tz = 1024, Dz = 1024, Hz = 16, HDz = 64;
constexpr int Mz = Bz * Tz;  // 8192 rows
constexpr float SCALE = 0.35355339059327373f;  // 64^(-1/4)
}

// Scratch (device globals: no allocation allowed in kernel_launch)
__device__ float g_q[(size_t)Mz * Dz];
__device__ float g_k[(size_t)Mz * Dz];
__device__ float g_v[(size_t)Mz * Dz];
__device__ float g_att[(size_t)Mz * Dz];

// ----------------------------------------------------------------------------
// GEMM: C[M,N] = alpha * (A[M,K] @ W[N,K]^T + bias[N])
// 128x128 tile, BK=32, 256 threads, 8x8 microtile per thread.
// ----------------------------------------------------------------------------
constexpr int BM = 128, BN = 128, BK = 32;

__global__ __launch_bounds__(256) void gemm_bias_kernel(
    const float* __restrict__ A, const float* __restrict__ W,
    const float* __restrict__ bias, float* __restrict__ C,
    int M, int N, int K, float alpha)
{
    __shared__ float As[BK][BM + 4];  // +4 keeps 16B alignment, tames conflicts
    __shared__ float Ws[BK][BN + 4];

    const int tid = threadIdx.x;
    const int bn = blockIdx.x * BN;
    const int bm = blockIdx.y * BM;
    const int tx = tid & 15;
    const int ty = tid >> 4;

    float acc[8][8];
#pragma unroll
    for (int i = 0; i < 8; i++)
#pragma unroll
        for (int j = 0; j < 8; j++) acc[i][j] = 0.f;

    for (int k0 = 0; k0 < K; k0 += BK) {
        // Load A tile (BM x BK) and W tile (BN x BK), stored k-major in smem.
#pragma unroll
        for (int i = 0; i < 4; i++) {
            int idx = i * 256 + tid;           // 1024 float4 slots
            int row = idx >> 3;                // 0..127
            int col = (idx & 7) << 2;          // 0,4,...,28
            float4 av = *reinterpret_cast<const float4*>(
                A + (size_t)(bm + row) * K + k0 + col);
            As[col + 0][row] = av.x; As[col + 1][row] = av.y;
            As[col + 2][row] = av.z; As[col + 3][row] = av.w;
            float4 wv = *reinterpret_cast<const float4*>(
                W + (size_t)(bn + row) * K + k0 + col);
            Ws[col + 0][row] = wv.x; Ws[col + 1][row] = wv.y;
            Ws[col + 2][row] = wv.z; Ws[col + 3][row] = wv.w;
        }
        __syncthreads();

#pragma unroll 4
        for (int kk = 0; kk < BK; kk++) {
            float a[8], b[8];
            *reinterpret_cast<float4*>(&a[0]) =
                *reinterpret_cast<const float4*>(&As[kk][ty * 8]);
            *reinterpret_cast<float4*>(&a[4]) =
                *reinterpret_cast<const float4*>(&As[kk][ty * 8 + 4]);
            *reinterpret_cast<float4*>(&b[0]) =
                *reinterpret_cast<const float4*>(&Ws[kk][tx * 8]);
            *reinterpret_cast<float4*>(&b[4]) =
                *reinterpret_cast<const float4*>(&Ws[kk][tx * 8 + 4]);
#pragma unroll
            for (int i = 0; i < 8; i++)
#pragma unroll
                for (int j = 0; j < 8; j++)
                    acc[i][j] += a[i] * b[j];
        }
        __syncthreads();
    }

#pragma unroll
    for (int i = 0; i < 8; i++) {
        int m = bm + ty * 8 + i;
#pragma unroll
        for (int j = 0; j < 8; j += 4) {
            int n = bn + tx * 8 + j;
            float4 o;
            o.x = alpha * (acc[i][j + 0] + (bias ? bias[n + 0] : 0.f));
            o.y = alpha * (acc[i][j + 1] + (bias ? bias[n + 1] : 0.f));
            o.z = alpha * (acc[i][j + 2] + (bias ? bias[n + 2] : 0.f));
            o.w = alpha * (acc[i][j + 3] + (bias ? bias[n + 3] : 0.f));
            *reinterpret_cast<float4*>(C + (size_t)m * N + n) = o;
        }
    }
}

// ----------------------------------------------------------------------------
// Causal flash-style attention. Grid: (T/BQ, H, B), 128 threads.
// Each thread owns one query row: Q and O accumulator in registers,
// K/V tiles (64x64) staged in smem. Streaming softmax without max
// subtraction (scores bounded ~|s|<6, exp safe in fp32; matches reference
// softmax semantics exactly up to fp rounding). Causal blocks beyond the
// diagonal are never visited.
// ----------------------------------------------------------------------------
constexpr int BQ = 128, BKV = 64;

__global__ __launch_bounds__(128) void attn_kernel()
{
    const int qb = blockIdx.x;
    const int h  = blockIdx.y;
    const int b  = blockIdx.z;
    const int tid = threadIdx.x;
    const int qg = qb * BQ + tid;  // global query index (0..1023)

    __shared__ float Ks[BKV][HDz];  // 16 KB
    __shared__ float Vs[BKV][HDz];  // 16 KB

    // Q row into registers (already scaled by 64^-0.25 during projection)
    float Q[HDz];
    {
        const float* qptr = g_q + ((size_t)b * Tz + qg) * Dz + h * HDz;
#pragma unroll
        for (int d = 0; d < HDz; d += 4)
            *reinterpret_cast<float4*>(&Q[d]) =
                *reinterpret_cast<const float4*>(qptr + d);
    }

    float O[HDz];
#pragma unroll
    for (int d = 0; d < HDz; d++) O[d] = 0.f;
    float l = 0.f;

    const int nkb = 2 * (qb + 1);  // key blocks needed under causal mask

    for (int jb = 0; jb < nkb; jb++) {
        const float* kbase = g_k + ((size_t)b * Tz + jb * BKV) * Dz + h * HDz;
        const float* vbase = g_v + ((size_t)b * Tz + jb * BKV) * Dz + h * HDz;
#pragma unroll
        for (int i = 0; i < 8; i++) {
            int idx = i * 128 + tid;     // 1024 float4 slots
            int r = idx >> 4;            // 0..63
            int c = (idx & 15) << 2;     // 0..60
            *reinterpret_cast<float4*>(&Ks[r][c]) =
                *reinterpret_cast<const float4*>(kbase + (size_t)r * Dz + c);
            *reinterpret_cast<float4*>(&Vs[r][c]) =
                *reinterpret_cast<const float4*>(vbase + (size_t)r * Dz + c);
        }
        __syncthreads();

        const int jbase = jb * BKV;
#pragma unroll 1
        for (int j = 0; j < BKV; j++) {
            // dot(Q, K[j]) with 4 independent accumulator chains for ILP
            float s0 = 0.f, s1 = 0.f, s2 = 0.f, s3 = 0.f;
#pragma unroll
            for (int d4 = 0; d4 < 16; d4 += 4) {
                float4 k0 = *reinterpret_cast<const float4*>(&Ks[j][d4 * 4]);
                float4 k1 = *reinterpret_cast<const float4*>(&Ks[j][d4 * 4 + 4]);
                float4 k2 = *reinterpret_cast<const float4*>(&Ks[j][d4 * 4 + 8]);
                float4 k3 = *reinterpret_cast<const float4*>(&Ks[j][d4 * 4 + 12]);
                s0 += Q[d4*4+0]*k0.x + Q[d4*4+1]*k0.y + Q[d4*4+2]*k0.z + Q[d4*4+3]*k0.w;
                s1 += Q[d4*4+4]*k1.x + Q[d4*4+5]*k1.y + Q[d4*4+6]*k1.z + Q[d4*4+7]*k1.w;
                s2 += Q[d4*4+8]*k2.x + Q[d4*4+9]*k2.y + Q[d4*4+10]*k2.z + Q[d4*4+11]*k2.w;
                s3 += Q[d4*4+12]*k3.x + Q[d4*4+13]*k3.y + Q[d4*4+14]*k3.z + Q[d4*4+15]*k3.w;
            }
            float s = (s0 + s1) + (s2 + s3);
            float p = (jbase + j <= qg) ? __expf(s) : 0.f;
            l += p;
#pragma unroll
            for (int d = 0; d < HDz; d += 4) {
                float4 vv = *reinterpret_cast<const float4*>(&Vs[j][d]);
                O[d + 0] += p * vv.x;
                O[d + 1] += p * vv.y;
                O[d + 2] += p * vv.z;
                O[d + 3] += p * vv.w;
            }
        }
        __syncthreads();
    }

    const float inv = 1.f / l;
    float* optr = g_att + ((size_t)b * Tz + qg) * Dz + h * HDz;
#pragma unroll
    for (int d = 0; d < HDz; d += 4) {
        float4 o;
        o.x = O[d + 0] * inv;
        o.y = O[d + 1] * inv;
        o.z = O[d + 2] * inv;
        o.w = O[d + 3] * inv;
        *reinterpret_cast<float4*>(optr + d) = o;
    }
}

// ----------------------------------------------------------------------------
// Launch. Input order (metadata): x, mask, Wq, bq, Wk, Wv, bv, Wo, bo.
// mask is unused (deterministic causal triu(-1e9); exp underflow == hard mask).
// ----------------------------------------------------------------------------
extern "C" void kernel_launch(void* const* d_in, const int* in_sizes, int n_in,
                              void* d_out, int out_size)
{
    const float* x  = (const float*)d_in[0];
    // d_in[1] = mask (unused)
    const float* Wq = (const float*)d_in[2];
    const float* bq = (const float*)d_in[3];
    const float* Wk = (const float*)d_in[4];
    const float* Wv = (const float*)d_in[5];
    const float* bv = (const float*)d_in[6];
    const float* Wo = (const float*)d_in[7];
    const float* bo = (const float*)d_in[8];
    float* out = (float*)d_out;

    float *p_q, *p_k, *p_v, *p_att;
    cudaGetSymbolAddress((void**)&p_q,   g_q);
    cudaGetSymbolAddress((void**)&p_k,   g_k);
    cudaGetSymbolAddress((void**)&p_v,   g_v);
    cudaGetSymbolAddress((void**)&p_att, g_att);

    dim3 ggrid(Dz / BN, Mz / BM);  // (8, 64)

    // Projections (scale folded into Q and K epilogues)
    gemm_bias_kernel<<<ggrid, 256>>>(x, Wq, bq,      p_q, Mz, Dz, Dz, SCALE);
    gemm_bias_kernel<<<ggrid, 256>>>(x, Wk, nullptr, p_k, Mz, Dz, Dz, SCALE);
    gemm_bias_kernel<<<ggrid, 256>>>(x, Wv, bv,      p_v, Mz, Dz, Dz, 1.0f);

    // Causal attention
    attn_kernel<<<dim3(Tz / BQ, Hz, Bz), 128>>>();

    // Output projection
    gemm_bias_kernel<<<ggrid, 256>>>(p_att, Wo, bo, out, Mz, Dz, Dz, 1.0f);
}

// round 3
// speedup vs baseline: 2.0427x; 2.0427x over previous
#include <cuda_runtime.h>
#include <cstdint>

// ============================================================================
// MultiHeadAttention: B=8, T=1024, D=1024, H=16, hd=64, fp32.
// R3: projection GEMMs via legacy mma.sync tf32 (sm_80 path — the sm_103
// non-'a' ptxas target used by the harness rejects tcgen05).
// Attention stays SIMT fp32 (next round).
// ============================================================================

namespace {
constexpr int Bz = 8, Tz = 1024, Dz = 1024, Hz = 16, HDz = 64;
constexpr int Mz = Bz * Tz;  // 8192 rows
constexpr float SCALE = 0.35355339059327373f;  // 64^(-1/4)
}

__device__ float g_q[(size_t)Mz * Dz];
__device__ float g_k[(size_t)Mz * Dz];
__device__ float g_v[(size_t)Mz * Dz];
__device__ float g_att[(size_t)Mz * Dz];

// ---------------------------------------------------------------------------
// PTX helpers
// ---------------------------------------------------------------------------
__device__ __forceinline__ uint32_t smem_u32(const void* p) {
    uint32_t a;
    asm("{ .reg .u64 t; cvta.to.shared.u64 t, %1; cvt.u32.u64 %0, t; }"
        : "=r"(a) : "l"(p));
    return a;
}
#define CP_ASYNC16(dst, src) \
    asm volatile("cp.async.cg.shared.global [%0], [%1], 16;" :: "r"(dst), "l"(src) : "memory")
#define CP_ASYNC_COMMIT() asm volatile("cp.async.commit_group;" ::: "memory")
#define CP_ASYNC_WAIT1()  asm volatile("cp.async.wait_group 1;" ::: "memory")
#define CP_ASYNC_WAIT0()  asm volatile("cp.async.wait_group 0;" ::: "memory")

__device__ __forceinline__ void ldmx4(uint32_t* r, uint32_t addr) {
    asm volatile("ldmatrix.sync.aligned.m8n8.x4.shared.b16 {%0, %1, %2, %3}, [%4];"
                 : "=r"(r[0]), "=r"(r[1]), "=r"(r[2]), "=r"(r[3]) : "r"(addr));
}
__device__ __forceinline__ uint32_t f2tf32(uint32_t x) {
    uint32_t o;
    asm("cvt.rna.tf32.f32 %0, %1;" : "=r"(o) : "f"(__uint_as_float(x)));
    return o;
}
__device__ __forceinline__ void mma_tf32(float* c, const uint32_t* a, const uint32_t* b) {
    asm volatile(
        "mma.sync.aligned.m16n8k8.row.col.f32.tf32.tf32.f32 "
        "{%0, %1, %2, %3}, {%4, %5, %6, %7}, {%8, %9}, {%0, %1, %2, %3};"
        : "+f"(c[0]), "+f"(c[1]), "+f"(c[2]), "+f"(c[3])
        : "r"(a[0]), "r"(a[1]), "r"(a[2]), "r"(a[3]), "r"(b[0]), "r"(b[1]));
}

// ---------------------------------------------------------------------------
// tf32 mma.sync GEMM: C[M,N] = alpha * (A[M,K] @ W[N,K]^T + bias[N])
// CTA: 128x128 tile, K-chunk 32 fp32, 3-stage cp.async pipeline, 256 threads.
// Warp (8 total, 4x2): 32(m) x 64(n) tile -> 2x8 m16n8 MMA tiles per k8 step.
// Smem: per stage A[128][32] + B[128][32] fp32, 16B-granule XOR swizzle.
// ---------------------------------------------------------------------------
constexpr int GTM = 128, GTN = 128, GCK = 32;
constexpr int GSTAGES = 3;
constexpr int NCHUNK = Dz / GCK;              // 32
constexpr int TILE_BYTES = GTM * GCK * 4;     // 16 KB (A or B)
constexpr int STAGE_BYTES = 2 * TILE_BYTES;   // 32 KB
constexpr int GSMEM = STAGE_BYTES * GSTAGES;  // 96 KB

__global__ __launch_bounds__(256) void gemm_tf32_kernel(
    const float* __restrict__ A, const float* __restrict__ W,
    const float* __restrict__ bias, float* __restrict__ C,
    int M, int N, int K, float alpha)
{
    extern __shared__ __align__(1024) char smem[];
    const uint32_t sbase = smem_u32(smem);

    const int tid = threadIdx.x;
    const int wid = tid >> 5, lane = tid & 31;
    const int bn = blockIdx.x * GTN;
    const int bm = blockIdx.y * GTM;
    const int wm = (wid & 3) * 32;    // warp m offset in tile
    const int wn = (wid >> 2) * 64;   // warp n offset in tile

    // cp.async source/dst for this thread: 8 granules per chunk
    // u = p*256 + tid; u<1024 -> A granule, else B. row r=u>>3 (or (u-1024)>>3), col granule c=u&7
    float acc[2][8][4];
#pragma unroll
    for (int i = 0; i < 2; i++)
#pragma unroll
        for (int j = 0; j < 8; j++)
#pragma unroll
            for (int q = 0; q < 4; q++) acc[i][j][q] = 0.f;

    auto issue_chunk = [&](int chunk) {
        const int k0 = chunk * GCK;
        const uint32_t st = sbase + (chunk % GSTAGES) * STAGE_BYTES;
#pragma unroll
        for (int p = 0; p < 8; p++) {
            int u = p * 256 + tid;
            if (u < 1024) {
                int r = u >> 3, c = u & 7;
                const float* src = A + (size_t)(bm + r) * K + k0 + c * 4;
                uint32_t dst = st + (uint32_t)(r * 128 + ((c ^ (r & 7)) << 4));
                CP_ASYNC16(dst, src);
            } else {
                int v = u - 1024;
                int r = v >> 3, c = v & 7;
                const float* src = W + (size_t)(bn + r) * K + k0 + c * 4;
                uint32_t dst = st + TILE_BYTES + (uint32_t)(r * 128 + ((c ^ (r & 7)) << 4));
                CP_ASYNC16(dst, src);
            }
        }
        CP_ASYNC_COMMIT();
    };

    issue_chunk(0);
    issue_chunk(1);

    // precompute lane-row decomposition for ldmatrix addressing
    const int lj = lane >> 3;   // matrix index 0..3
    const int lr = lane & 7;    // row within matrix

    for (int chunk = 0; chunk < NCHUNK; chunk++) {
        CP_ASYNC_WAIT1();
        __syncthreads();
        if (chunk + 2 < NCHUNK) issue_chunk(chunk + 2);

        const uint32_t st = sbase + (chunk % GSTAGES) * STAGE_BYTES;
        const uint32_t sA = st, sB = st + TILE_BYTES;

#pragma unroll
        for (int ks = 0; ks < 4; ks++) {
            const int g = 2 * ks;  // k granule base for this k8 step

            // A fragments: 2 m16 tiles
            uint32_t a[2][4];
#pragma unroll
            for (int i = 0; i < 2; i++) {
                // matrices: j0:(m0..7,g) j1:(m8..15,g) j2:(m0..7,g+1) j3:(m8..15,g+1)
                int mrow = wm + i * 16 + (lj & 1) * 8 + lr;
                int gcol = g + (lj >> 1);
                uint32_t addr = sA + (uint32_t)(mrow * 128 + ((gcol ^ (mrow & 7)) << 4));
                ldmx4(a[i], addr);
#pragma unroll
                for (int q = 0; q < 4; q++) a[i][q] = f2tf32(a[i][q]);
            }
            // B fragments: 4 x4-ldmatrix covering n64 (16 n per ldmatrix)
            uint32_t b[4][4];
#pragma unroll
            for (int jg = 0; jg < 4; jg++) {
                // matrices: j0:(n0..7,g) j1:(n0..7,g+1) j2:(n8..15,g) j3:(n8..15,g+1)
                int nrow = wn + jg * 16 + (lj >> 1) * 8 + lr;
                int gcol = g + (lj & 1);
                uint32_t addr = sB + (uint32_t)(nrow * 128 + ((gcol ^ (nrow & 7)) << 4));
                ldmx4(b[jg], addr);
#pragma unroll
                for (int q = 0; q < 4; q++) b[jg][q] = f2tf32(b[jg][q]);
            }
#pragma unroll
            for (int i = 0; i < 2; i++)
#pragma unroll
                for (int jt = 0; jt < 8; jt++) {
                    uint32_t bp[2] = { b[jt >> 1][(jt & 1) * 2 + 0],
                                       b[jt >> 1][(jt & 1) * 2 + 1] };
                    mma_tf32(acc[i][jt], a[i], bp);
                }
        }
        __syncthreads();   // everyone done reading this stage before overwrite
    }
    CP_ASYNC_WAIT0();

    // Epilogue: c fragment (m16n8): c0,c1 at (row=lane>>2, col=(lane&3)*2 +0/1),
    // c2,c3 at row+8. float2 stores.
    const int er = lane >> 2, ec = (lane & 3) * 2;
#pragma unroll
    for (int jt = 0; jt < 8; jt++) {
        int n = bn + wn + jt * 8 + ec;
        float2 bv = bias ? *reinterpret_cast<const float2*>(bias + n)
                         : make_float2(0.f, 0.f);
#pragma unroll
        for (int i = 0; i < 2; i++) {
            int m0 = bm + wm + i * 16 + er;
            float2 o0, o1;
            o0.x = alpha * (acc[i][jt][0] + bv.x);
            o0.y = alpha * (acc[i][jt][1] + bv.y);
            o1.x = alpha * (acc[i][jt][2] + bv.x);
            o1.y = alpha * (acc[i][jt][3] + bv.y);
            *reinterpret_cast<float2*>(C + (size_t)m0 * N + n) = o0;
            *reinterpret_cast<float2*>(C + (size_t)(m0 + 8) * N + n) = o1;
        }
    }
}

// ----------------------------------------------------------------------------
// Causal flash-style attention (unchanged from R1). Grid: (T/128, H, B).
// ----------------------------------------------------------------------------
constexpr int BQ = 128, BKV = 64;

__global__ __launch_bounds__(128) void attn_kernel()
{
    const int qb = blockIdx.x;
    const int h  = blockIdx.y;
    const int b  = blockIdx.z;
    const int tid = threadIdx.x;
    const int qg = qb * BQ + tid;

    __shared__ float Ks[BKV][HDz];
    __shared__ float Vs[BKV][HDz];

    float Q[HDz];
    {
        const float* qptr = g_q + ((size_t)b * Tz + qg) * Dz + h * HDz;
#pragma unroll
        for (int d = 0; d < HDz; d += 4)
            *reinterpret_cast<float4*>(&Q[d]) =
                *reinterpret_cast<const float4*>(qptr + d);
    }

    float O[HDz];
#pragma unroll
    for (int d = 0; d < HDz; d++) O[d] = 0.f;
    float l = 0.f;

    const int nkb = 2 * (qb + 1);

    for (int jb = 0; jb < nkb; jb++) {
        const float* kbase = g_k + ((size_t)b * Tz + jb * BKV) * Dz + h * HDz;
        const float* vbase = g_v + ((size_t)b * Tz + jb * BKV) * Dz + h * HDz;
#pragma unroll
        for (int i = 0; i < 8; i++) {
            int idx = i * 128 + tid;
            int r = idx >> 4;
            int c = (idx & 15) << 2;
            *reinterpret_cast<float4*>(&Ks[r][c]) =
                *reinterpret_cast<const float4*>(kbase + (size_t)r * Dz + c);
            *reinterpret_cast<float4*>(&Vs[r][c]) =
                *reinterpret_cast<const float4*>(vbase + (size_t)r * Dz + c);
        }
        __syncthreads();

        const int jbase = jb * BKV;
#pragma unroll 1
        for (int j = 0; j < BKV; j++) {
            float s0 = 0.f, s1 = 0.f, s2 = 0.f, s3 = 0.f;
#pragma unroll
            for (int d4 = 0; d4 < 16; d4 += 4) {
                float4 k0 = *reinterpret_cast<const float4*>(&Ks[j][d4 * 4]);
                float4 k1 = *reinterpret_cast<const float4*>(&Ks[j][d4 * 4 + 4]);
                float4 k2 = *reinterpret_cast<const float4*>(&Ks[j][d4 * 4 + 8]);
                float4 k3 = *reinterpret_cast<const float4*>(&Ks[j][d4 * 4 + 12]);
                s0 += Q[d4*4+0]*k0.x + Q[d4*4+1]*k0.y + Q[d4*4+2]*k0.z + Q[d4*4+3]*k0.w;
                s1 += Q[d4*4+4]*k1.x + Q[d4*4+5]*k1.y + Q[d4*4+6]*k1.z + Q[d4*4+7]*k1.w;
                s2 += Q[d4*4+8]*k2.x + Q[d4*4+9]*k2.y + Q[d4*4+10]*k2.z + Q[d4*4+11]*k2.w;
                s3 += Q[d4*4+12]*k3.x + Q[d4*4+13]*k3.y + Q[d4*4+14]*k3.z + Q[d4*4+15]*k3.w;
            }
            float s = (s0 + s1) + (s2 + s3);
            float p = (jbase + j <= qg) ? __expf(s) : 0.f;
            l += p;
#pragma unroll
            for (int d = 0; d < HDz; d += 4) {
                float4 vv = *reinterpret_cast<const float4*>(&Vs[j][d]);
                O[d + 0] += p * vv.x;
                O[d + 1] += p * vv.y;
                O[d + 2] += p * vv.z;
                O[d + 3] += p * vv.w;
            }
        }
        __syncthreads();
    }

    const float inv = 1.f / l;
    float* optr = g_att + ((size_t)b * Tz + qg) * Dz + h * HDz;
#pragma unroll
    for (int d = 0; d < HDz; d += 4) {
        float4 o;
        o.x = O[d + 0] * inv;
        o.y = O[d + 1] * inv;
        o.z = O[d + 2] * inv;
        o.w = O[d + 3] * inv;
        *reinterpret_cast<float4*>(optr + d) = o;
    }
}

// ----------------------------------------------------------------------------
// Launch. Inputs: x, mask(unused), Wq, bq, Wk, Wv, bv, Wo, bo.
// ----------------------------------------------------------------------------
extern "C" void kernel_launch(void* const* d_in, const int* in_sizes, int n_in,
                              void* d_out, int out_size)
{
    const float* x  = (const float*)d_in[0];
    const float* Wq = (const float*)d_in[2];
    const float* bq = (const float*)d_in[3];
    const float* Wk = (const float*)d_in[4];
    const float* Wv = (const float*)d_in[5];
    const float* bv = (const float*)d_in[6];
    const float* Wo = (const float*)d_in[7];
    const float* bo = (const float*)d_in[8];
    float* out = (float*)d_out;

    float *p_q, *p_k, *p_v, *p_att;
    cudaGetSymbolAddress((void**)&p_q,   g_q);
    cudaGetSymbolAddress((void**)&p_k,   g_k);
    cudaGetSymbolAddress((void**)&p_v,   g_v);
    cudaGetSymbolAddress((void**)&p_att, g_att);

    cudaFuncSetAttribute(gemm_tf32_kernel,
                         cudaFuncAttributeMaxDynamicSharedMemorySize, GSMEM);

    dim3 ggrid(Dz / GTN, Mz / GTM);  // (8, 64)

    gemm_tf32_kernel<<<ggrid, 256, GSMEM>>>(x, Wq, bq,      p_q, Mz, Dz, Dz, SCALE);
    gemm_tf32_kernel<<<ggrid, 256, GSMEM>>>(x, Wk, nullptr, p_k, Mz, Dz, Dz, SCALE);
    gemm_tf32_kernel<<<ggrid, 256, GSMEM>>>(x, Wv, bv,      p_v, Mz, Dz, Dz, 1.0f);

    attn_kernel<<<dim3(Tz / BQ, Hz, Bz), 128>>>();

    gemm_tf32_kernel<<<ggrid, 256, GSMEM>>>(p_att, Wo, bo, out, Mz, Dz, Dz, 1.0f);
}

// round 5
// speedup vs baseline: 2.4487x; 1.1988x over previous
#include <cuda_runtime.h>
#include <cstdint>

// ============================================================================
// MultiHeadAttention: B=8, T=1024, D=1024, H=16, hd=64, fp32.
// R4: tensor-core (mma.sync tf32) flash attention + FFMA-only exp2 softmax.
// Projection GEMMs unchanged from R3 (mma.sync tf32, cp.async 3-stage).
// ============================================================================

namespace {
constexpr int Bz = 8, Tz = 1024, Dz = 1024, Hz = 16, HDz = 64;
constexpr int Mz = Bz * Tz;  // 8192 rows
// 64^(-1/4) * sqrt(log2(e)): scores come out of QK^T already in log2 domain.
constexpr float SCALE_QK = 0.35355339059327373f * 1.2011224087864498f;
}

__device__ float g_q[(size_t)Mz * Dz];
__device__ float g_k[(size_t)Mz * Dz];
__device__ float g_v[(size_t)Mz * Dz];
__device__ float g_att[(size_t)Mz * Dz];

// ---------------------------------------------------------------------------
// PTX helpers
// ---------------------------------------------------------------------------
__device__ __forceinline__ uint32_t smem_u32(const void* p) {
    uint32_t a;
    asm("{ .reg .u64 t; cvta.to.shared.u64 t, %1; cvt.u32.u64 %0, t; }"
        : "=r"(a) : "l"(p));
    return a;
}
#define CP_ASYNC16(dst, src) \
    asm volatile("cp.async.cg.shared.global [%0], [%1], 16;" :: "r"(dst), "l"(src) : "memory")
#define CP_ASYNC_COMMIT() asm volatile("cp.async.commit_group;" ::: "memory")
#define CP_ASYNC_WAIT1()  asm volatile("cp.async.wait_group 1;" ::: "memory")
#define CP_ASYNC_WAIT0()  asm volatile("cp.async.wait_group 0;" ::: "memory")

__device__ __forceinline__ void ldmx4(uint32_t* r, uint32_t addr) {
    asm volatile("ldmatrix.sync.aligned.m8n8.x4.shared.b16 {%0, %1, %2, %3}, [%4];"
                 : "=r"(r[0]), "=r"(r[1]), "=r"(r[2]), "=r"(r[3]) : "r"(addr));
}
__device__ __forceinline__ uint32_t f2tf32(uint32_t x) {
    uint32_t o;
    asm("cvt.rna.tf32.f32 %0, %1;" : "=r"(o) : "f"(__uint_as_float(x)));
    return o;
}
__device__ __forceinline__ void mma_tf32(float* c, const uint32_t* a, const uint32_t* b) {
    asm volatile(
        "mma.sync.aligned.m16n8k8.row.col.f32.tf32.tf32.f32 "
        "{%0, %1, %2, %3}, {%4, %5, %6, %7}, {%8, %9}, {%0, %1, %2, %3};"
        : "+f"(c[0]), "+f"(c[1]), "+f"(c[2]), "+f"(c[3])
        : "r"(a[0]), "r"(a[1]), "r"(a[2]), "r"(a[3]), "r"(b[0]), "r"(b[1]));
}

// FFMA-only 2^y (y already in log2 domain). |y| < ~30. Max rel err ~2.4e-6.
__device__ __forceinline__ float fexp2(float y) {
    float z = __fadd_rn(y, 12582912.0f);            // round-to-nearest int in mantissa
    int e = __float_as_int(z) - 0x4B400000;         // integer part
    float f = __fsub_rn(y, __fsub_rn(z, 12582912.0f));  // frac in [-0.5, 0.5]
    float p = fmaf(f, 0.0013333558f, 0.0096181291f);
    p = fmaf(p, f, 0.0555041087f);
    p = fmaf(p, f, 0.2402265069f);
    p = fmaf(p, f, 0.6931471806f);
    p = fmaf(p, f, 1.0f);
    return p * __int_as_float((e + 127) << 23);
}

// ---------------------------------------------------------------------------
// tf32 mma.sync GEMM (unchanged from R3): C = alpha*(A @ W^T + bias)
// ---------------------------------------------------------------------------
constexpr int GTM = 128, GTN = 128, GCK = 32;
constexpr int GSTAGES = 3;
constexpr int NCHUNK = Dz / GCK;
constexpr int TILE_BYTES = GTM * GCK * 4;
constexpr int STAGE_BYTES = 2 * TILE_BYTES;
constexpr int GSMEM = STAGE_BYTES * GSTAGES;

__global__ __launch_bounds__(256) void gemm_tf32_kernel(
    const float* __restrict__ A, const float* __restrict__ W,
    const float* __restrict__ bias, float* __restrict__ C,
    int M, int N, int K, float alpha)
{
    extern __shared__ __align__(1024) char smem[];
    const uint32_t sbase = smem_u32(smem);

    const int tid = threadIdx.x;
    const int wid = tid >> 5, lane = tid & 31;
    const int bn = blockIdx.x * GTN;
    const int bm = blockIdx.y * GTM;
    const int wm = (wid & 3) * 32;
    const int wn = (wid >> 2) * 64;

    float acc[2][8][4];
#pragma unroll
    for (int i = 0; i < 2; i++)
#pragma unroll
        for (int j = 0; j < 8; j++)
#pragma unroll
            for (int q = 0; q < 4; q++) acc[i][j][q] = 0.f;

    auto issue_chunk = [&](int chunk) {
        const int k0 = chunk * GCK;
        const uint32_t st = sbase + (chunk % GSTAGES) * STAGE_BYTES;
#pragma unroll
        for (int p = 0; p < 8; p++) {
            int u = p * 256 + tid;
            if (u < 1024) {
                int r = u >> 3, c = u & 7;
                const float* src = A + (size_t)(bm + r) * K + k0 + c * 4;
                uint32_t dst = st + (uint32_t)(r * 128 + ((c ^ (r & 7)) << 4));
                CP_ASYNC16(dst, src);
            } else {
                int v = u - 1024;
                int r = v >> 3, c = v & 7;
                const float* src = W + (size_t)(bn + r) * K + k0 + c * 4;
                uint32_t dst = st + TILE_BYTES + (uint32_t)(r * 128 + ((c ^ (r & 7)) << 4));
                CP_ASYNC16(dst, src);
            }
        }
        CP_ASYNC_COMMIT();
    };

    issue_chunk(0);
    issue_chunk(1);

    const int lj = lane >> 3;
    const int lr = lane & 7;

    for (int chunk = 0; chunk < NCHUNK; chunk++) {
        CP_ASYNC_WAIT1();
        __syncthreads();
        if (chunk + 2 < NCHUNK) issue_chunk(chunk + 2);

        const uint32_t st = sbase + (chunk % GSTAGES) * STAGE_BYTES;
        const uint32_t sA = st, sB = st + TILE_BYTES;

#pragma unroll
        for (int ks = 0; ks < 4; ks++) {
            const int g = 2 * ks;
            uint32_t a[2][4];
#pragma unroll
            for (int i = 0; i < 2; i++) {
                int mrow = wm + i * 16 + (lj & 1) * 8 + lr;
                int gcol = g + (lj >> 1);
                uint32_t addr = sA + (uint32_t)(mrow * 128 + ((gcol ^ (mrow & 7)) << 4));
                ldmx4(a[i], addr);
#pragma unroll
                for (int q = 0; q < 4; q++) a[i][q] = f2tf32(a[i][q]);
            }
            uint32_t b[4][4];
#pragma unroll
            for (int jg = 0; jg < 4; jg++) {
                int nrow = wn + jg * 16 + (lj >> 1) * 8 + lr;
                int gcol = g + (lj & 1);
                uint32_t addr = sB + (uint32_t)(nrow * 128 + ((gcol ^ (nrow & 7)) << 4));
                ldmx4(b[jg], addr);
#pragma unroll
                for (int q = 0; q < 4; q++) b[jg][q] = f2tf32(b[jg][q]);
            }
#pragma unroll
            for (int i = 0; i < 2; i++)
#pragma unroll
                for (int jt = 0; jt < 8; jt++) {
                    uint32_t bp[2] = { b[jt >> 1][(jt & 1) * 2 + 0],
                                       b[jt >> 1][(jt & 1) * 2 + 1] };
                    mma_tf32(acc[i][jt], a[i], bp);
                }
        }
        __syncthreads();
    }
    CP_ASYNC_WAIT0();

    const int er = lane >> 2, ec = (lane & 3) * 2;
#pragma unroll
    for (int jt = 0; jt < 8; jt++) {
        int n = bn + wn + jt * 8 + ec;
        float2 bv = bias ? *reinterpret_cast<const float2*>(bias + n)
                         : make_float2(0.f, 0.f);
#pragma unroll
        for (int i = 0; i < 2; i++) {
            int m0 = bm + wm + i * 16 + er;
            float2 o0, o1;
            o0.x = alpha * (acc[i][jt][0] + bv.x);
            o0.y = alpha * (acc[i][jt][1] + bv.y);
            o1.x = alpha * (acc[i][jt][2] + bv.x);
            o1.y = alpha * (acc[i][jt][3] + bv.y);
            *reinterpret_cast<float2*>(C + (size_t)m0 * N + n) = o0;
            *reinterpret_cast<float2*>(C + (size_t)(m0 + 8) * N + n) = o1;
        }
    }
}

// ---------------------------------------------------------------------------
// Tensor-core causal flash attention.
// Grid (8, H, B); CTA = 256 thr (8 warps), BQ=128 (16 q-rows/warp), BKV=64.
// Per kv-block: S = Q@K^T (tf32 mma) -> ffma-exp2 softmax (streaming, max-free,
// scores already log2-scaled) -> stage P to swizzled smem -> O += P@V^T via Vt.
// Rows of Q/K/P/Vt tiles = 64 floats = 16 granules; swizzle low 3 granule bits.
// ---------------------------------------------------------------------------
constexpr int AQ = 128, AKV = 64;
constexpr int O_Q  = 0;        // 32 KB
constexpr int O_K  = 32768;    // 2 x 16 KB
constexpr int O_VR = 65536;    // 2 x 16 KB (untransposed V stages)
constexpr int O_VT = 98304;    // 16 KB (V^T, [d][j])
constexpr int O_P  = 114688;   // 32 KB (8 warps x 16 x 64)
constexpr int ASMEM = 147456 + 1024;

__device__ __forceinline__ uint32_t swz16(int row, int gg) {
    return (uint32_t)((gg & 8) | ((gg & 7) ^ (row & 7)));
}

__global__ __launch_bounds__(256, 1) void attn_kernel()
{
    const int qb = (int)gridDim.x - 1 - (int)blockIdx.x;  // heavy CTAs first
    const int h = blockIdx.y, b = blockIdx.z;

    extern __shared__ char smem_raw[];
    const uint32_t raw = smem_u32(smem_raw);
    const uint32_t sb = (raw + 1023u) & ~1023u;
    char* smem = smem_raw + (sb - raw);

    const int tid = threadIdx.x, lane = tid & 31, wq = tid >> 5;
    const int grp = lane >> 2, qtid = lane & 3;
    const int lj = lane >> 3, lr = lane & 7;

    const float* Qg = g_q + ((size_t)(b * Tz + qb * AQ)) * Dz + h * HDz;
    const float* Kg = g_k + ((size_t)b * Tz) * Dz + h * HDz;
    const float* Vg = g_v + ((size_t)b * Tz) * Dz + h * HDz;

    const int nkb = 2 * qb + 2;

    auto load_kv = [&](int jb) {
        const int st = jb & 1;
        const float* kp = Kg + (size_t)(jb * AKV) * Dz;
        const float* vp = Vg + (size_t)(jb * AKV) * Dz;
#pragma unroll
        for (int p = 0; p < 4; p++) {
            int idx = p * 256 + tid;       // 1024 float4 each
            int r = idx >> 4, gg = idx & 15;
            CP_ASYNC16(sb + O_K + st * 16384 + r * 256 + swz16(r, gg) * 16,
                       kp + (size_t)r * Dz + gg * 4);
            CP_ASYNC16(sb + O_VR + st * 16384 + r * 256 + gg * 16,
                       vp + (size_t)r * Dz + gg * 4);
        }
    };

    // Prologue: Q + kv block 0 (group 0), kv block 1 (group 1)
#pragma unroll
    for (int p = 0; p < 8; p++) {
        int idx = p * 256 + tid;           // 2048 float4
        int r = idx >> 4, gg = idx & 15;
        CP_ASYNC16(sb + O_Q + r * 256 + swz16(r, gg) * 16,
                   Qg + (size_t)r * Dz + gg * 4);
    }
    load_kv(0);
    CP_ASYNC_COMMIT();
    load_kv(1);   // nkb >= 2 always
    CP_ASYNC_COMMIT();

    float ofr[8][4];
#pragma unroll
    for (int i = 0; i < 8; i++)
#pragma unroll
        for (int q = 0; q < 4; q++) ofr[i][q] = 0.f;
    float l_lo = 0.f, l_hi = 0.f;

    const int qrow_lo = qb * AQ + wq * 16 + grp;   // this thread's low q row
    const uint32_t pwarp = sb + O_P + wq * 4096;

    for (int jb = 0; jb < nkb; jb++) {
        const int st = jb & 1;
        CP_ASYNC_WAIT1();
        __syncthreads();   // stage ready; prev PV done (Vt free)

        // --- transpose V stage -> Vt[d][j] (swizzled) ---
        {
            const float4* vr = reinterpret_cast<const float4*>(smem + O_VR + st * 16384);
            float* vt = reinterpret_cast<float*>(smem + O_VT);
#pragma unroll
            for (int p = 0; p < 4; p++) {
                int idx = p * 256 + tid;
                int j = idx >> 4, gg = idx & 15;
                float4 v = vr[idx];
                int d0 = gg * 4;
                vt[(d0 + 0) * 64 + swz16(d0 + 0, j >> 2) * 4 + (j & 3)] = v.x;
                vt[(d0 + 1) * 64 + swz16(d0 + 1, j >> 2) * 4 + (j & 3)] = v.y;
                vt[(d0 + 2) * 64 + swz16(d0 + 2, j >> 2) * 4 + (j & 3)] = v.z;
                vt[(d0 + 3) * 64 + swz16(d0 + 3, j >> 2) * 4 + (j & 3)] = v.w;
            }
        }

        // --- S = Q @ K^T for this warp's 16 rows x 64 kv ---
        float sfr[8][4];
#pragma unroll
        for (int i = 0; i < 8; i++)
#pragma unroll
            for (int q = 0; q < 4; q++) sfr[i][q] = 0.f;

        const uint32_t qbase = sb + O_Q + (wq * 16) * 256;
        const uint32_t kbase = sb + O_K + st * 16384;
#pragma unroll
        for (int ks = 0; ks < 8; ks++) {
            uint32_t a[4];
            {
                int row = (lj & 1) * 8 + lr;
                int gg = 2 * ks + (lj >> 1);
                ldmx4(a, qbase + row * 256 + swz16(row, gg) * 16);
#pragma unroll
                for (int q = 0; q < 4; q++) a[q] = f2tf32(a[q]);
            }
#pragma unroll
            for (int jg = 0; jg < 4; jg++) {
                uint32_t bfr[4];
                int nrow = jg * 16 + (lj >> 1) * 8 + lr;
                int gg = 2 * ks + (lj & 1);
                ldmx4(bfr, kbase + nrow * 256 + swz16(nrow, gg) * 16);
#pragma unroll
                for (int q = 0; q < 4; q++) bfr[q] = f2tf32(bfr[q]);
                uint32_t b0[2] = { bfr[0], bfr[1] };
                uint32_t b1[2] = { bfr[2], bfr[3] };
                mma_tf32(sfr[jg * 2 + 0], a, b0);
                mma_tf32(sfr[jg * 2 + 1], a, b1);
            }
        }

        // --- softmax (log2-domain scores) + causal mask + stage P ---
        const bool need_mask = (jb >= 2 * qb);
#pragma unroll
        for (int jt = 0; jt < 8; jt++) {
            float p0 = fexp2(sfr[jt][0]);
            float p1 = fexp2(sfr[jt][1]);
            float p2 = fexp2(sfr[jt][2]);
            float p3 = fexp2(sfr[jt][3]);
            if (need_mask) {
                int j0 = jb * AKV + jt * 8 + qtid * 2;
                p0 = (j0     <= qrow_lo)     ? p0 : 0.f;
                p1 = (j0 + 1 <= qrow_lo)     ? p1 : 0.f;
                p2 = (j0     <= qrow_lo + 8) ? p2 : 0.f;
                p3 = (j0 + 1 <= qrow_lo + 8) ? p3 : 0.f;
            }
            l_lo += p0 + p1;
            l_hi += p2 + p3;
            int jl = jt * 8 + qtid * 2;
            int gg = jl >> 2, off = jl & 3;
            *reinterpret_cast<float2*>(
                smem + (pwarp - sb) + grp * 256 + swz16(grp, gg) * 16 + off * 4) =
                make_float2(p0, p1);
            *reinterpret_cast<float2*>(
                smem + (pwarp - sb) + (grp + 8) * 256 + swz16(grp + 8, gg) * 16 + off * 4) =
                make_float2(p2, p3);
        }

        __syncthreads();   // Vt + all P staged; K stage consumed
        if (jb + 2 < nkb) load_kv(jb + 2);
        CP_ASYNC_COMMIT();

        // --- O += P @ V (B operand from Vt[d][j]) ---
        const uint32_t vtbase = sb + O_VT;
#pragma unroll
        for (int ks = 0; ks < 8; ks++) {
            uint32_t a[4];
            {
                int row = (lj & 1) * 8 + lr;
                int gg = 2 * ks + (lj >> 1);
                ldmx4(a, pwarp + row * 256 + swz16(row, gg) * 16);
#pragma unroll
                for (int q = 0; q < 4; q++) a[q] = f2tf32(a[q]);
            }
#pragma unroll
            for (int jg = 0; jg < 4; jg++) {
                uint32_t bfr[4];
                int nrow = jg * 16 + (lj >> 1) * 8 + lr;   // d row
                int gg = 2 * ks + (lj & 1);
                ldmx4(bfr, vtbase + nrow * 256 + swz16(nrow, gg) * 16);
#pragma unroll
                for (int q = 0; q < 4; q++) bfr[q] = f2tf32(bfr[q]);
                uint32_t b0[2] = { bfr[0], bfr[1] };
                uint32_t b1[2] = { bfr[2], bfr[3] };
                mma_tf32(ofr[jg * 2 + 0], a, b0);
                mma_tf32(ofr[jg * 2 + 1], a, b1);
            }
        }
    }

    // --- finalize: row sums across quad, divide, store ---
    l_lo += __shfl_xor_sync(0xFFFFFFFF, l_lo, 1);
    l_lo += __shfl_xor_sync(0xFFFFFFFF, l_lo, 2);
    l_hi += __shfl_xor_sync(0xFFFFFFFF, l_hi, 1);
    l_hi += __shfl_xor_sync(0xFFFFFFFF, l_hi, 2);
    const float inv_lo = 1.f / l_lo, inv_hi = 1.f / l_hi;

    const int q_lo = qb * AQ + wq * 16 + grp;
#pragma unroll
    for (int jt = 0; jt < 8; jt++) {
        int d = jt * 8 + qtid * 2;
        float* base_lo = g_att + ((size_t)(b * Tz + q_lo) * Dz) + h * HDz + d;
        float* base_hi = base_lo + (size_t)8 * Dz;
        *reinterpret_cast<float2*>(base_lo) =
            make_float2(ofr[jt][0] * inv_lo, ofr[jt][1] * inv_lo);
        *reinterpret_cast<float2*>(base_hi) =
            make_float2(ofr[jt][2] * inv_hi, ofr[jt][3] * inv_hi);
    }
}

// ----------------------------------------------------------------------------
// Launch. Inputs: x, mask(unused), Wq, bq, Wk, Wv, bv, Wo, bo.
// ----------------------------------------------------------------------------
extern "C" void kernel_launch(void* const* d_in, const int* in_sizes, int n_in,
                              void* d_out, int out_size)
{
    const float* x  = (const float*)d_in[0];
    const float* Wq = (const float*)d_in[2];
    const float* bq = (const float*)d_in[3];
    const float* Wk = (const float*)d_in[4];
    const float* Wv = (const float*)d_in[5];
    const float* bv = (const float*)d_in[6];
    const float* Wo = (const float*)d_in[7];
    const float* bo = (const float*)d_in[8];
    float* out = (float*)d_out;

    float *p_q, *p_k, *p_v, *p_att;
    cudaGetSymbolAddress((void**)&p_q,   g_q);
    cudaGetSymbolAddress((void**)&p_k,   g_k);
    cudaGetSymbolAddress((void**)&p_v,   g_v);
    cudaGetSymbolAddress((void**)&p_att, g_att);

    cudaFuncSetAttribute(gemm_tf32_kernel,
                         cudaFuncAttributeMaxDynamicSharedMemorySize, GSMEM);
    cudaFuncSetAttribute(attn_kernel,
                         cudaFuncAttributeMaxDynamicSharedMemorySize, ASMEM);

    dim3 ggrid(Dz / GTN, Mz / GTM);  // (8, 64)

    gemm_tf32_kernel<<<ggrid, 256, GSMEM>>>(x, Wq, bq,      p_q, Mz, Dz, Dz, SCALE_QK);
    gemm_tf32_kernel<<<ggrid, 256, GSMEM>>>(x, Wk, nullptr, p_k, Mz, Dz, Dz, SCALE_QK);
    gemm_tf32_kernel<<<ggrid, 256, GSMEM>>>(x, Wv, bv,      p_v, Mz, Dz, Dz, 1.0f);

    attn_kernel<<<dim3(Tz / AQ, Hz, Bz), 256, ASMEM>>>();

    gemm_tf32_kernel<<<ggrid, 256, GSMEM>>>(p_att, Wo, bo, out, Mz, Dz, Dz, 1.0f);
}

// round 6
// speedup vs baseline: 4.3068x; 1.7588x over previous
#include <cuda_runtime.h>
#include <cstdint>

// ============================================================================
// MultiHeadAttention: B=8, T=1024, D=1024, H=16, hd=64, fp32.
// R6: producers emit tf32-pre-rounded q/k/v/att; attention keeps Q fragments
// in registers (Q smem reused for P staging); all in-loop cvt.rna removed.
// QKV projection GEMMs fused into one launch.
// ============================================================================

namespace {
constexpr int Bz = 8, Tz = 1024, Dz = 1024, Hz = 16, HDz = 64;
constexpr int Mz = Bz * Tz;  // 8192 rows
// 64^(-1/4) * sqrt(log2(e)): scores come out of QK^T already in log2 domain.
constexpr float SCALE_QK = 0.35355339059327373f * 1.2011224087864498f;
}

__device__ float g_q[(size_t)Mz * Dz];
__device__ float g_k[(size_t)Mz * Dz];
__device__ float g_v[(size_t)Mz * Dz];
__device__ float g_att[(size_t)Mz * Dz];

// ---------------------------------------------------------------------------
// PTX helpers
// ---------------------------------------------------------------------------
__device__ __forceinline__ uint32_t smem_u32(const void* p) {
    uint32_t a;
    asm("{ .reg .u64 t; cvta.to.shared.u64 t, %1; cvt.u32.u64 %0, t; }"
        : "=r"(a) : "l"(p));
    return a;
}
#define CP_ASYNC16(dst, src) \
    asm volatile("cp.async.cg.shared.global [%0], [%1], 16;" :: "r"(dst), "l"(src) : "memory")
#define CP_ASYNC_COMMIT() asm volatile("cp.async.commit_group;" ::: "memory")
#define CP_ASYNC_WAIT1()  asm volatile("cp.async.wait_group 1;" ::: "memory")
#define CP_ASYNC_WAIT0()  asm volatile("cp.async.wait_group 0;" ::: "memory")

__device__ __forceinline__ void ldmx4(uint32_t* r, uint32_t addr) {
    asm volatile("ldmatrix.sync.aligned.m8n8.x4.shared.b16 {%0, %1, %2, %3}, [%4];"
                 : "=r"(r[0]), "=r"(r[1]), "=r"(r[2]), "=r"(r[3]) : "r"(addr));
}
__device__ __forceinline__ uint32_t f2tf32(uint32_t x) {
    uint32_t o;
    asm("cvt.rna.tf32.f32 %0, %1;" : "=r"(o) : "f"(__uint_as_float(x)));
    return o;
}
__device__ __forceinline__ float ftf(float x) {
    return __uint_as_float(f2tf32(__float_as_uint(x)));
}
__device__ __forceinline__ void mma_tf32(float* c, const uint32_t* a, const uint32_t* b) {
    asm volatile(
        "mma.sync.aligned.m16n8k8.row.col.f32.tf32.tf32.f32 "
        "{%0, %1, %2, %3}, {%4, %5, %6, %7}, {%8, %9}, {%0, %1, %2, %3};"
        : "+f"(c[0]), "+f"(c[1]), "+f"(c[2]), "+f"(c[3])
        : "r"(a[0]), "r"(a[1]), "r"(a[2]), "r"(a[3]), "r"(b[0]), "r"(b[1]));
}

// FFMA-only 2^y (y already in log2 domain). Max rel err ~2.4e-6.
__device__ __forceinline__ float fexp2(float y) {
    float z = __fadd_rn(y, 12582912.0f);
    int e = __float_as_int(z) - 0x4B400000;
    float f = __fsub_rn(y, __fsub_rn(z, 12582912.0f));
    float p = fmaf(f, 0.0013333558f, 0.0096181291f);
    p = fmaf(p, f, 0.0555041087f);
    p = fmaf(p, f, 0.2402265069f);
    p = fmaf(p, f, 0.6931471806f);
    p = fmaf(p, f, 1.0f);
    return p * __int_as_float((e + 127) << 23);
}

// ---------------------------------------------------------------------------
// tf32 mma.sync GEMM body: C = alpha*(A @ W^T + bias), M=N=K fixed (8192/1024).
// 128x128 tile, K-chunk 32, 3-stage cp.async, 8 warps x (32x64). If round_out,
// stores are tf32(rna)-rounded so consumers can skip fragment cvt.
// ---------------------------------------------------------------------------
constexpr int GTN = 128, GCK = 32;
constexpr int GSTAGES = 3;
constexpr int NCHUNK = Dz / GCK;
constexpr int TILE_BYTES = 128 * GCK * 4;
constexpr int STAGE_BYTES = 2 * TILE_BYTES;
constexpr int GSMEM = STAGE_BYTES * GSTAGES;

__device__ __forceinline__ void gemm_body(
    const float* __restrict__ A, const float* __restrict__ W,
    const float* __restrict__ bias, float* __restrict__ C,
    float alpha, bool round_out, char* smem)
{
    const uint32_t sbase = smem_u32(smem);
    const int K = Dz, N = Dz;

    const int tid = threadIdx.x;
    const int wid = tid >> 5, lane = tid & 31;
    const int bn = blockIdx.x * GTN;
    const int bm = blockIdx.y * 128;
    const int wm = (wid & 3) * 32;
    const int wn = (wid >> 2) * 64;

    float acc[2][8][4];
#pragma unroll
    for (int i = 0; i < 2; i++)
#pragma unroll
        for (int j = 0; j < 8; j++)
#pragma unroll
            for (int q = 0; q < 4; q++) acc[i][j][q] = 0.f;

    auto issue_chunk = [&](int chunk) {
        const int k0 = chunk * GCK;
        const uint32_t st = sbase + (chunk % GSTAGES) * STAGE_BYTES;
#pragma unroll
        for (int p = 0; p < 8; p++) {
            int u = p * 256 + tid;
            if (u < 1024) {
                int r = u >> 3, c = u & 7;
                const float* src = A + (size_t)(bm + r) * K + k0 + c * 4;
                uint32_t dst = st + (uint32_t)(r * 128 + ((c ^ (r & 7)) << 4));
                CP_ASYNC16(dst, src);
            } else {
                int v = u - 1024;
                int r = v >> 3, c = v & 7;
                const float* src = W + (size_t)(bn + r) * K + k0 + c * 4;
                uint32_t dst = st + TILE_BYTES + (uint32_t)(r * 128 + ((c ^ (r & 7)) << 4));
                CP_ASYNC16(dst, src);
            }
        }
        CP_ASYNC_COMMIT();
    };

    issue_chunk(0);
    issue_chunk(1);

    const int lj = lane >> 3;
    const int lr = lane & 7;

    for (int chunk = 0; chunk < NCHUNK; chunk++) {
        CP_ASYNC_WAIT1();
        __syncthreads();
        if (chunk + 2 < NCHUNK) issue_chunk(chunk + 2);

        const uint32_t st = sbase + (chunk % GSTAGES) * STAGE_BYTES;
        const uint32_t sA = st, sB = st + TILE_BYTES;

#pragma unroll
        for (int ks = 0; ks < 4; ks++) {
            const int g = 2 * ks;
            uint32_t a[2][4];
#pragma unroll
            for (int i = 0; i < 2; i++) {
                int mrow = wm + i * 16 + (lj & 1) * 8 + lr;
                int gcol = g + (lj >> 1);
                uint32_t addr = sA + (uint32_t)(mrow * 128 + ((gcol ^ (mrow & 7)) << 4));
                ldmx4(a[i], addr);
#pragma unroll
                for (int q = 0; q < 4; q++) a[i][q] = f2tf32(a[i][q]);
            }
            uint32_t b[4][4];
#pragma unroll
            for (int jg = 0; jg < 4; jg++) {
                int nrow = wn + jg * 16 + (lj >> 1) * 8 + lr;
                int gcol = g + (lj & 1);
                uint32_t addr = sB + (uint32_t)(nrow * 128 + ((gcol ^ (nrow & 7)) << 4));
                ldmx4(b[jg], addr);
#pragma unroll
                for (int q = 0; q < 4; q++) b[jg][q] = f2tf32(b[jg][q]);
            }
#pragma unroll
            for (int i = 0; i < 2; i++)
#pragma unroll
                for (int jt = 0; jt < 8; jt++) {
                    uint32_t bp[2] = { b[jt >> 1][(jt & 1) * 2 + 0],
                                       b[jt >> 1][(jt & 1) * 2 + 1] };
                    mma_tf32(acc[i][jt], a[i], bp);
                }
        }
        __syncthreads();
    }
    CP_ASYNC_WAIT0();

    const int er = lane >> 2, ec = (lane & 3) * 2;
#pragma unroll
    for (int jt = 0; jt < 8; jt++) {
        int n = bn + wn + jt * 8 + ec;
        float2 bv = bias ? *reinterpret_cast<const float2*>(bias + n)
                         : make_float2(0.f, 0.f);
#pragma unroll
        for (int i = 0; i < 2; i++) {
            int m0 = bm + wm + i * 16 + er;
            float2 o0, o1;
            o0.x = alpha * (acc[i][jt][0] + bv.x);
            o0.y = alpha * (acc[i][jt][1] + bv.y);
            o1.x = alpha * (acc[i][jt][2] + bv.x);
            o1.y = alpha * (acc[i][jt][3] + bv.y);
            if (round_out) {
                o0.x = ftf(o0.x); o0.y = ftf(o0.y);
                o1.x = ftf(o1.x); o1.y = ftf(o1.y);
            }
            *reinterpret_cast<float2*>(C + (size_t)m0 * N + n) = o0;
            *reinterpret_cast<float2*>(C + (size_t)(m0 + 8) * N + n) = o1;
        }
    }
}

// Fused Q/K/V projections: blockIdx.z selects the GEMM.
__global__ __launch_bounds__(256) void qkv_gemm_kernel(
    const float* __restrict__ x,
    const float* __restrict__ Wq, const float* __restrict__ bq,
    const float* __restrict__ Wk,
    const float* __restrict__ Wv, const float* __restrict__ bv,
    float* __restrict__ pq, float* __restrict__ pk, float* __restrict__ pv)
{
    extern __shared__ __align__(1024) char smem[];
    if (blockIdx.z == 0)      gemm_body(x, Wq, bq,      pq, SCALE_QK, true, smem);
    else if (blockIdx.z == 1) gemm_body(x, Wk, nullptr, pk, SCALE_QK, true, smem);
    else                      gemm_body(x, Wv, bv,      pv, 1.0f,     true, smem);
}

__global__ __launch_bounds__(256) void out_gemm_kernel(
    const float* __restrict__ att, const float* __restrict__ Wo,
    const float* __restrict__ bo, float* __restrict__ out)
{
    extern __shared__ __align__(1024) char smem[];
    gemm_body(att, Wo, bo, out, 1.0f, false, smem);
}

// ---------------------------------------------------------------------------
// Tensor-core causal flash attention.
// Grid (8, H, B); CTA = 256 thr (8 warps), BQ=128 (16 q-rows/warp), BKV=64.
// Q fragments live in registers (loaded once); Q smem region is reused as the
// P staging buffer. q/k/v are tf32-pre-rounded by the GEMMs -> no in-loop cvt.
// ---------------------------------------------------------------------------
constexpr int AQ = 128, AKV = 64;
constexpr int O_Q  = 0;        // 32 KB: Q during prologue, then P staging
constexpr int O_K  = 32768;    // 2 x 16 KB
constexpr int O_VR = 65536;    // 2 x 16 KB (untransposed V stages)
constexpr int O_VT = 98304;    // 16 KB (V^T, [d][j])
constexpr int ASMEM = 114688 + 1024;

__device__ __forceinline__ uint32_t swz16(int row, int gg) {
    return (uint32_t)((gg & 8) | ((gg & 7) ^ (row & 7)));
}

__global__ __launch_bounds__(256, 1) void attn_kernel()
{
    const int qb = (int)gridDim.x - 1 - (int)blockIdx.x;  // heavy CTAs first
    const int h = blockIdx.y, b = blockIdx.z;

    extern __shared__ char smem_raw[];
    const uint32_t raw = smem_u32(smem_raw);
    const uint32_t sb = (raw + 1023u) & ~1023u;
    char* smem = smem_raw + (sb - raw);

    const int tid = threadIdx.x, lane = tid & 31, wq = tid >> 5;
    const int grp = lane >> 2, qtid = lane & 3;
    const int lj = lane >> 3, lr = lane & 7;

    const float* Qg = g_q + ((size_t)(b * Tz + qb * AQ)) * Dz + h * HDz;
    const float* Kg = g_k + ((size_t)b * Tz) * Dz + h * HDz;
    const float* Vg = g_v + ((size_t)b * Tz) * Dz + h * HDz;

    const int nkb = 2 * qb + 2;

    auto load_kv = [&](int jb) {
        const int st = jb & 1;
        const float* kp = Kg + (size_t)(jb * AKV) * Dz;
        const float* vp = Vg + (size_t)(jb * AKV) * Dz;
#pragma unroll
        for (int p = 0; p < 4; p++) {
            int idx = p * 256 + tid;
            int r = idx >> 4, gg = idx & 15;
            CP_ASYNC16(sb + O_K + st * 16384 + r * 256 + swz16(r, gg) * 16,
                       kp + (size_t)r * Dz + gg * 4);
            CP_ASYNC16(sb + O_VR + st * 16384 + r * 256 + gg * 16,
                       vp + (size_t)r * Dz + gg * 4);
        }
    };

    // Prologue: Q (group 0 with kv0), kv1 in group 1.
#pragma unroll
    for (int p = 0; p < 8; p++) {
        int idx = p * 256 + tid;
        int r = idx >> 4, gg = idx & 15;
        CP_ASYNC16(sb + O_Q + r * 256 + swz16(r, gg) * 16,
                   Qg + (size_t)r * Dz + gg * 4);
    }
    load_kv(0);
    CP_ASYNC_COMMIT();
    load_kv(1);
    CP_ASYNC_COMMIT();

    uint32_t qf[8][4];   // Q fragments, loaded once at jb==0
    float ofr[8][4];
#pragma unroll
    for (int i = 0; i < 8; i++)
#pragma unroll
        for (int q = 0; q < 4; q++) ofr[i][q] = 0.f;
    float l_lo = 0.f, l_hi = 0.f;

    const int qrow_lo = qb * AQ + wq * 16 + grp;
    const uint32_t pwarp = sb + O_Q + wq * 4096;   // P staging = old Q slice

    for (int jb = 0; jb < nkb; jb++) {
        const int st = jb & 1;
        CP_ASYNC_WAIT1();
        __syncthreads();

        if (jb == 0) {
            // Load this warp's Q fragments into registers (pre-rounded tf32).
            const uint32_t qbase = sb + O_Q + (wq * 16) * 256;
#pragma unroll
            for (int ks = 0; ks < 8; ks++) {
                int row = (lj & 1) * 8 + lr;
                int gg = 2 * ks + (lj >> 1);
                ldmx4(qf[ks], qbase + row * 256 + swz16(row, gg) * 16);
            }
        }

        // --- transpose V stage -> Vt[d][j] (values already tf32-rounded) ---
        {
            const float4* vr = reinterpret_cast<const float4*>(smem + O_VR + st * 16384);
            float* vt = reinterpret_cast<float*>(smem + O_VT);
#pragma unroll
            for (int p = 0; p < 4; p++) {
                int idx = p * 256 + tid;
                int j = idx >> 4, gg = idx & 15;
                float4 v = vr[idx];
                int d0 = gg * 4;
                vt[(d0 + 0) * 64 + swz16(d0 + 0, j >> 2) * 4 + (j & 3)] = v.x;
                vt[(d0 + 1) * 64 + swz16(d0 + 1, j >> 2) * 4 + (j & 3)] = v.y;
                vt[(d0 + 2) * 64 + swz16(d0 + 2, j >> 2) * 4 + (j & 3)] = v.z;
                vt[(d0 + 3) * 64 + swz16(d0 + 3, j >> 2) * 4 + (j & 3)] = v.w;
            }
        }

        // --- S = Q @ K^T (no cvt: operands pre-rounded) ---
        float sfr[8][4];
#pragma unroll
        for (int i = 0; i < 8; i++)
#pragma unroll
            for (int q = 0; q < 4; q++) sfr[i][q] = 0.f;

        const uint32_t kbase = sb + O_K + st * 16384;
#pragma unroll
        for (int ks = 0; ks < 8; ks++) {
#pragma unroll
            for (int jg = 0; jg < 4; jg++) {
                uint32_t bfr[4];
                int nrow = jg * 16 + (lj >> 1) * 8 + lr;
                int gg = 2 * ks + (lj & 1);
                ldmx4(bfr, kbase + nrow * 256 + swz16(nrow, gg) * 16);
                uint32_t b0[2] = { bfr[0], bfr[1] };
                uint32_t b1[2] = { bfr[2], bfr[3] };
                mma_tf32(sfr[jg * 2 + 0], qf[ks], b0);
                mma_tf32(sfr[jg * 2 + 1], qf[ks], b1);
            }
        }

        // --- softmax (log2 domain) + causal mask + stage tf32-rounded P ---
        const bool need_mask = (jb >= 2 * qb);
#pragma unroll
        for (int jt = 0; jt < 8; jt++) {
            float p0 = fexp2(sfr[jt][0]);
            float p1 = fexp2(sfr[jt][1]);
            float p2 = fexp2(sfr[jt][2]);
            float p3 = fexp2(sfr[jt][3]);
            if (need_mask) {
                int j0 = jb * AKV + jt * 8 + qtid * 2;
                p0 = (j0     <= qrow_lo)     ? p0 : 0.f;
                p1 = (j0 + 1 <= qrow_lo)     ? p1 : 0.f;
                p2 = (j0     <= qrow_lo + 8) ? p2 : 0.f;
                p3 = (j0 + 1 <= qrow_lo + 8) ? p3 : 0.f;
            }
            l_lo += p0 + p1;
            l_hi += p2 + p3;
            int jl = jt * 8 + qtid * 2;
            int gg = jl >> 2, off = jl & 3;
            *reinterpret_cast<float2*>(
                smem + (pwarp - sb) + grp * 256 + swz16(grp, gg) * 16 + off * 4) =
                make_float2(ftf(p0), ftf(p1));
            *reinterpret_cast<float2*>(
                smem + (pwarp - sb) + (grp + 8) * 256 + swz16(grp + 8, gg) * 16 + off * 4) =
                make_float2(ftf(p2), ftf(p3));
        }

        __syncthreads();   // Vt + all P staged; K stage consumed
        if (jb + 2 < nkb) load_kv(jb + 2);
        CP_ASYNC_COMMIT();

        // --- O += P @ V (operands pre-rounded; no cvt) ---
        const uint32_t vtbase = sb + O_VT;
#pragma unroll
        for (int ks = 0; ks < 8; ks++) {
            uint32_t a[4];
            {
                int row = (lj & 1) * 8 + lr;
                int gg = 2 * ks + (lj >> 1);
                ldmx4(a, pwarp + row * 256 + swz16(row, gg) * 16);
            }
#pragma unroll
            for (int jg = 0; jg < 4; jg++) {
                uint32_t bfr[4];
                int nrow = jg * 16 + (lj >> 1) * 8 + lr;
                int gg = 2 * ks + (lj & 1);
                ldmx4(bfr, vtbase + nrow * 256 + swz16(nrow, gg) * 16);
                uint32_t b0[2] = { bfr[0], bfr[1] };
                uint32_t b1[2] = { bfr[2], bfr[3] };
                mma_tf32(ofr[jg * 2 + 0], a, b0);
                mma_tf32(ofr[jg * 2 + 1], a, b1);
            }
        }
    }

    // --- finalize: quad row sums, divide, store tf32-rounded att ---
    l_lo += __shfl_xor_sync(0xFFFFFFFF, l_lo, 1);
    l_lo += __shfl_xor_sync(0xFFFFFFFF, l_lo, 2);
    l_hi += __shfl_xor_sync(0xFFFFFFFF, l_hi, 1);
    l_hi += __shfl_xor_sync(0xFFFFFFFF, l_hi, 2);
    const float inv_lo = 1.f / l_lo, inv_hi = 1.f / l_hi;

    const int q_lo = qb * AQ + wq * 16 + grp;
#pragma unroll
    for (int jt = 0; jt < 8; jt++) {
        int d = jt * 8 + qtid * 2;
        float* base_lo = g_att + ((size_t)(b * Tz + q_lo) * Dz) + h * HDz + d;
        float* base_hi = base_lo + (size_t)8 * Dz;
        *reinterpret_cast<float2*>(base_lo) =
            make_float2(ftf(ofr[jt][0] * inv_lo), ftf(ofr[jt][1] * inv_lo));
        *reinterpret_cast<float2*>(base_hi) =
            make_float2(ftf(ofr[jt][2] * inv_hi), ftf(ofr[jt][3] * inv_hi));
    }
}

// ----------------------------------------------------------------------------
// Launch. Inputs: x, mask(unused), Wq, bq, Wk, Wv, bv, Wo, bo.
// ----------------------------------------------------------------------------
extern "C" void kernel_launch(void* const* d_in, const int* in_sizes, int n_in,
                              void* d_out, int out_size)
{
    const float* x  = (const float*)d_in[0];
    const float* Wq = (const float*)d_in[2];
    const float* bq = (const float*)d_in[3];
    const float* Wk = (const float*)d_in[4];
    const float* Wv = (const float*)d_in[5];
    const float* bv = (const float*)d_in[6];
    const float* Wo = (const float*)d_in[7];
    const float* bo = (const float*)d_in[8];
    float* out = (float*)d_out;

    float *p_q, *p_k, *p_v, *p_att;
    cudaGetSymbolAddress((void**)&p_q,   g_q);
    cudaGetSymbolAddress((void**)&p_k,   g_k);
    cudaGetSymbolAddress((void**)&p_v,   g_v);
    cudaGetSymbolAddress((void**)&p_att, g_att);

    cudaFuncSetAttribute(qkv_gemm_kernel,
                         cudaFuncAttributeMaxDynamicSharedMemorySize, GSMEM);
    cudaFuncSetAttribute(out_gemm_kernel,
                         cudaFuncAttributeMaxDynamicSharedMemorySize, GSMEM);
    cudaFuncSetAttribute(attn_kernel,
                         cudaFuncAttributeMaxDynamicSharedMemorySize, ASMEM);

    qkv_gemm_kernel<<<dim3(Dz / GTN, Mz / 128, 3), 256, GSMEM>>>(
        x, Wq, bq, Wk, Wv, bv, p_q, p_k, p_v);

    attn_kernel<<<dim3(Tz / AQ, Hz, Bz), 256, ASMEM>>>();

    out_gemm_kernel<<<dim3(Dz / GTN, Mz / 128), 256, GSMEM>>>(p_att, Wo, bo, out);
}

// round 7
// speedup vs baseline: 4.5886x; 1.0654x over previous
#include <cuda_runtime.h>
#include <cstdint>

// ============================================================================
// MultiHeadAttention: B=8, T=1024, D=1024, H=16, hd=64, fp32.
// R7: pre-round x and all weights to tf32 once; ALL GEMM in-loop cvt.rna
// removed (operands arrive pre-rounded). Attention unchanged from R6.
// ============================================================================

namespace {
constexpr int Bz = 8, Tz = 1024, Dz = 1024, Hz = 16, HDz = 64;
constexpr int Mz = Bz * Tz;  // 8192 rows
// 64^(-1/4) * sqrt(log2(e)): scores come out of QK^T already in log2 domain.
constexpr float SCALE_QK = 0.35355339059327373f * 1.2011224087864498f;
}

__device__ float g_q[(size_t)Mz * Dz];
__device__ float g_k[(size_t)Mz * Dz];
__device__ float g_v[(size_t)Mz * Dz];
__device__ float g_att[(size_t)Mz * Dz];
__device__ float g_xr[(size_t)Mz * Dz];        // tf32-rounded x
__device__ float g_wr[4][(size_t)Dz * Dz];     // tf32-rounded Wq, Wk, Wv, Wo

// ---------------------------------------------------------------------------
// PTX helpers
// ---------------------------------------------------------------------------
__device__ __forceinline__ uint32_t smem_u32(const void* p) {
    uint32_t a;
    asm("{ .reg .u64 t; cvta.to.shared.u64 t, %1; cvt.u32.u64 %0, t; }"
        : "=r"(a) : "l"(p));
    return a;
}
#define CP_ASYNC16(dst, src) \
    asm volatile("cp.async.cg.shared.global [%0], [%1], 16;" :: "r"(dst), "l"(src) : "memory")
#define CP_ASYNC_COMMIT() asm volatile("cp.async.commit_group;" ::: "memory")
#define CP_ASYNC_WAIT1()  asm volatile("cp.async.wait_group 1;" ::: "memory")
#define CP_ASYNC_WAIT0()  asm volatile("cp.async.wait_group 0;" ::: "memory")

__device__ __forceinline__ void ldmx4(uint32_t* r, uint32_t addr) {
    asm volatile("ldmatrix.sync.aligned.m8n8.x4.shared.b16 {%0, %1, %2, %3}, [%4];"
                 : "=r"(r[0]), "=r"(r[1]), "=r"(r[2]), "=r"(r[3]) : "r"(addr));
}
__device__ __forceinline__ uint32_t f2tf32(uint32_t x) {
    uint32_t o;
    asm("cvt.rna.tf32.f32 %0, %1;" : "=r"(o) : "f"(__uint_as_float(x)));
    return o;
}
__device__ __forceinline__ float ftf(float x) {
    return __uint_as_float(f2tf32(__float_as_uint(x)));
}
__device__ __forceinline__ void mma_tf32(float* c, const uint32_t* a, const uint32_t* b) {
    asm volatile(
        "mma.sync.aligned.m16n8k8.row.col.f32.tf32.tf32.f32 "
        "{%0, %1, %2, %3}, {%4, %5, %6, %7}, {%8, %9}, {%0, %1, %2, %3};"
        : "+f"(c[0]), "+f"(c[1]), "+f"(c[2]), "+f"(c[3])
        : "r"(a[0]), "r"(a[1]), "r"(a[2]), "r"(a[3]), "r"(b[0]), "r"(b[1]));
}

// FFMA-only 2^y (y already in log2 domain). Max rel err ~2.4e-6.
__device__ __forceinline__ float fexp2(float y) {
    float z = __fadd_rn(y, 12582912.0f);
    int e = __float_as_int(z) - 0x4B400000;
    float f = __fsub_rn(y, __fsub_rn(z, 12582912.0f));
    float p = fmaf(f, 0.0013333558f, 0.0096181291f);
    p = fmaf(p, f, 0.0555041087f);
    p = fmaf(p, f, 0.2402265069f);
    p = fmaf(p, f, 0.6931471806f);
    p = fmaf(p, f, 1.0f);
    return p * __int_as_float((e + 127) << 23);
}

// ---------------------------------------------------------------------------
// Pre-round: x and the 4 weight matrices -> tf32(rna) copies.
// One launch; float4 per thread; index ranges select the buffer.
// ---------------------------------------------------------------------------
constexpr int NX4 = Mz * Dz / 4;   // 2,097,152
constexpr int NW4 = Dz * Dz / 4;   //   262,144
constexpr int NPR = NX4 + 4 * NW4; // 3,145,728

__global__ __launch_bounds__(256) void preround_kernel(
    const float4* __restrict__ x,
    const float4* __restrict__ Wq, const float4* __restrict__ Wk,
    const float4* __restrict__ Wv, const float4* __restrict__ Wo)
{
    int i = blockIdx.x * blockDim.x + threadIdx.x;
    if (i >= NPR) return;
    const float4* src;
    float4* dst;
    if (i < NX4) {
        src = x + i;
        dst = reinterpret_cast<float4*>(g_xr) + i;
    } else {
        int j = i - NX4;
        int w = j / NW4, o = j % NW4;
        const float4* ws[4] = { Wq, Wk, Wv, Wo };
        src = ws[w] + o;
        dst = reinterpret_cast<float4*>(g_wr[w]) + o;
    }
    float4 v = *src;
    v.x = ftf(v.x); v.y = ftf(v.y); v.z = ftf(v.z); v.w = ftf(v.w);
    *dst = v;
}

// ---------------------------------------------------------------------------
// tf32 mma.sync GEMM body: C = alpha*(A @ W^T + bias). A and W arrive
// tf32-pre-rounded -> no in-loop cvt. 128x128 tile, K-chunk 32, 3 stages.
// ---------------------------------------------------------------------------
constexpr int GTN = 128, GCK = 32;
constexpr int GSTAGES = 3;
constexpr int NCHUNK = Dz / GCK;
constexpr int TILE_BYTES = 128 * GCK * 4;
constexpr int STAGE_BYTES = 2 * TILE_BYTES;
constexpr int GSMEM = STAGE_BYTES * GSTAGES;

__device__ __forceinline__ void gemm_body(
    const float* __restrict__ A, const float* __restrict__ W,
    const float* __restrict__ bias, float* __restrict__ C,
    float alpha, bool round_out, char* smem)
{
    const uint32_t sbase = smem_u32(smem);
    const int K = Dz, N = Dz;

    const int tid = threadIdx.x;
    const int wid = tid >> 5, lane = tid & 31;
    const int bn = blockIdx.x * GTN;
    const int bm = blockIdx.y * 128;
    const int wm = (wid & 3) * 32;
    const int wn = (wid >> 2) * 64;

    float acc[2][8][4];
#pragma unroll
    for (int i = 0; i < 2; i++)
#pragma unroll
        for (int j = 0; j < 8; j++)
#pragma unroll
            for (int q = 0; q < 4; q++) acc[i][j][q] = 0.f;

    auto issue_chunk = [&](int chunk) {
        const int k0 = chunk * GCK;
        const uint32_t st = sbase + (chunk % GSTAGES) * STAGE_BYTES;
#pragma unroll
        for (int p = 0; p < 8; p++) {
            int u = p * 256 + tid;
            if (u < 1024) {
                int r = u >> 3, c = u & 7;
                const float* src = A + (size_t)(bm + r) * K + k0 + c * 4;
                uint32_t dst = st + (uint32_t)(r * 128 + ((c ^ (r & 7)) << 4));
                CP_ASYNC16(dst, src);
            } else {
                int v = u - 1024;
                int r = v >> 3, c = v & 7;
                const float* src = W + (size_t)(bn + r) * K + k0 + c * 4;
                uint32_t dst = st + TILE_BYTES + (uint32_t)(r * 128 + ((c ^ (r & 7)) << 4));
                CP_ASYNC16(dst, src);
            }
        }
        CP_ASYNC_COMMIT();
    };

    issue_chunk(0);
    issue_chunk(1);

    const int lj = lane >> 3;
    const int lr = lane & 7;

    for (int chunk = 0; chunk < NCHUNK; chunk++) {
        CP_ASYNC_WAIT1();
        __syncthreads();
        if (chunk + 2 < NCHUNK) issue_chunk(chunk + 2);

        const uint32_t st = sbase + (chunk % GSTAGES) * STAGE_BYTES;
        const uint32_t sA = st, sB = st + TILE_BYTES;

#pragma unroll
        for (int ks = 0; ks < 4; ks++) {
            const int g = 2 * ks;
            uint32_t a[2][4];
#pragma unroll
            for (int i = 0; i < 2; i++) {
                int mrow = wm + i * 16 + (lj & 1) * 8 + lr;
                int gcol = g + (lj >> 1);
                uint32_t addr = sA + (uint32_t)(mrow * 128 + ((gcol ^ (mrow & 7)) << 4));
                ldmx4(a[i], addr);
            }
            uint32_t b[4][4];
#pragma unroll
            for (int jg = 0; jg < 4; jg++) {
                int nrow = wn + jg * 16 + (lj >> 1) * 8 + lr;
                int gcol = g + (lj & 1);
                uint32_t addr = sB + (uint32_t)(nrow * 128 + ((gcol ^ (nrow & 7)) << 4));
                ldmx4(b[jg], addr);
            }
#pragma unroll
            for (int i = 0; i < 2; i++)
#pragma unroll
                for (int jt = 0; jt < 8; jt++) {
                    uint32_t bp[2] = { b[jt >> 1][(jt & 1) * 2 + 0],
                                       b[jt >> 1][(jt & 1) * 2 + 1] };
                    mma_tf32(acc[i][jt], a[i], bp);
                }
        }
        __syncthreads();
    }
    CP_ASYNC_WAIT0();

    const int er = lane >> 2, ec = (lane & 3) * 2;
#pragma unroll
    for (int jt = 0; jt < 8; jt++) {
        int n = bn + wn + jt * 8 + ec;
        float2 bv = bias ? *reinterpret_cast<const float2*>(bias + n)
                         : make_float2(0.f, 0.f);
#pragma unroll
        for (int i = 0; i < 2; i++) {
            int m0 = bm + wm + i * 16 + er;
            float2 o0, o1;
            o0.x = alpha * (acc[i][jt][0] + bv.x);
            o0.y = alpha * (acc[i][jt][1] + bv.y);
            o1.x = alpha * (acc[i][jt][2] + bv.x);
            o1.y = alpha * (acc[i][jt][3] + bv.y);
            if (round_out) {
                o0.x = ftf(o0.x); o0.y = ftf(o0.y);
                o1.x = ftf(o1.x); o1.y = ftf(o1.y);
            }
            *reinterpret_cast<float2*>(C + (size_t)m0 * N + n) = o0;
            *reinterpret_cast<float2*>(C + (size_t)(m0 + 8) * N + n) = o1;
        }
    }
}

// Fused Q/K/V projections: blockIdx.z selects the GEMM (pre-rounded inputs).
__global__ __launch_bounds__(256) void qkv_gemm_kernel(
    const float* __restrict__ bq, const float* __restrict__ bv,
    float* __restrict__ pq, float* __restrict__ pk, float* __restrict__ pv)
{
    extern __shared__ __align__(1024) char smem[];
    if (blockIdx.z == 0)      gemm_body(g_xr, g_wr[0], bq,      pq, SCALE_QK, true, smem);
    else if (blockIdx.z == 1) gemm_body(g_xr, g_wr[1], nullptr, pk, SCALE_QK, true, smem);
    else                      gemm_body(g_xr, g_wr[2], bv,      pv, 1.0f,     true, smem);
}

__global__ __launch_bounds__(256) void out_gemm_kernel(
    const float* __restrict__ att, const float* __restrict__ bo,
    float* __restrict__ out)
{
    extern __shared__ __align__(1024) char smem[];
    gemm_body(att, g_wr[3], bo, out, 1.0f, false, smem);
}

// ---------------------------------------------------------------------------
// Tensor-core causal flash attention (unchanged from R6).
// ---------------------------------------------------------------------------
constexpr int AQ = 128, AKV = 64;
constexpr int O_Q  = 0;        // 32 KB: Q during prologue, then P staging
constexpr int O_K  = 32768;    // 2 x 16 KB
constexpr int O_VR = 65536;    // 2 x 16 KB (untransposed V stages)
constexpr int O_VT = 98304;    // 16 KB (V^T, [d][j])
constexpr int ASMEM = 114688 + 1024;

__device__ __forceinline__ uint32_t swz16(int row, int gg) {
    return (uint32_t)((gg & 8) | ((gg & 7) ^ (row & 7)));
}

__global__ __launch_bounds__(256, 1) void attn_kernel()
{
    const int qb = (int)gridDim.x - 1 - (int)blockIdx.x;  // heavy CTAs first
    const int h = blockIdx.y, b = blockIdx.z;

    extern __shared__ char smem_raw[];
    const uint32_t raw = smem_u32(smem_raw);
    const uint32_t sb = (raw + 1023u) & ~1023u;
    char* smem = smem_raw + (sb - raw);

    const int tid = threadIdx.x, lane = tid & 31, wq = tid >> 5;
    const int grp = lane >> 2, qtid = lane & 3;
    const int lj = lane >> 3, lr = lane & 7;

    const float* Qg = g_q + ((size_t)(b * Tz + qb * AQ)) * Dz + h * HDz;
    const float* Kg = g_k + ((size_t)b * Tz) * Dz + h * HDz;
    const float* Vg = g_v + ((size_t)b * Tz) * Dz + h * HDz;

    const int nkb = 2 * qb + 2;

    auto load_kv = [&](int jb) {
        const int st = jb & 1;
        const float* kp = Kg + (size_t)(jb * AKV) * Dz;
        const float* vp = Vg + (size_t)(jb * AKV) * Dz;
#pragma unroll
        for (int p = 0; p < 4; p++) {
            int idx = p * 256 + tid;
            int r = idx >> 4, gg = idx & 15;
            CP_ASYNC16(sb + O_K + st * 16384 + r * 256 + swz16(r, gg) * 16,
                       kp + (size_t)r * Dz + gg * 4);
            CP_ASYNC16(sb + O_VR + st * 16384 + r * 256 + gg * 16,
                       vp + (size_t)r * Dz + gg * 4);
        }
    };

    // Prologue: Q (group 0 with kv0), kv1 in group 1.
#pragma unroll
    for (int p = 0; p < 8; p++) {
        int idx = p * 256 + tid;
        int r = idx >> 4, gg = idx & 15;
        CP_ASYNC16(sb + O_Q + r * 256 + swz16(r, gg) * 16,
                   Qg + (size_t)r * Dz + gg * 4);
    }
    load_kv(0);
    CP_ASYNC_COMMIT();
    load_kv(1);
    CP_ASYNC_COMMIT();

    uint32_t qf[8][4];   // Q fragments, loaded once at jb==0
    float ofr[8][4];
#pragma unroll
    for (int i = 0; i < 8; i++)
#pragma unroll
        for (int q = 0; q < 4; q++) ofr[i][q] = 0.f;
    float l_lo = 0.f, l_hi = 0.f;

    const int qrow_lo = qb * AQ + wq * 16 + grp;
    const uint32_t pwarp = sb + O_Q + wq * 4096;   // P staging = old Q slice

    for (int jb = 0; jb < nkb; jb++) {
        const int st = jb & 1;
        CP_ASYNC_WAIT1();
        __syncthreads();

        if (jb == 0) {
            const uint32_t qbase = sb + O_Q + (wq * 16) * 256;
#pragma unroll
            for (int ks = 0; ks < 8; ks++) {
                int row = (lj & 1) * 8 + lr;
                int gg = 2 * ks + (lj >> 1);
                ldmx4(qf[ks], qbase + row * 256 + swz16(row, gg) * 16);
            }
        }

        // --- transpose V stage -> Vt[d][j] ---
        {
            const float4* vr = reinterpret_cast<const float4*>(smem + O_VR + st * 16384);
            float* vt = reinterpret_cast<float*>(smem + O_VT);
#pragma unroll
            for (int p = 0; p < 4; p++) {
                int idx = p * 256 + tid;
                int j = idx >> 4, gg = idx & 15;
                float4 v = vr[idx];
                int d0 = gg * 4;
                vt[(d0 + 0) * 64 + swz16(d0 + 0, j >> 2) * 4 + (j & 3)] = v.x;
                vt[(d0 + 1) * 64 + swz16(d0 + 1, j >> 2) * 4 + (j & 3)] = v.y;
                vt[(d0 + 2) * 64 + swz16(d0 + 2, j >> 2) * 4 + (j & 3)] = v.z;
                vt[(d0 + 3) * 64 + swz16(d0 + 3, j >> 2) * 4 + (j & 3)] = v.w;
            }
        }

        // --- S = Q @ K^T ---
        float sfr[8][4];
#pragma unroll
        for (int i = 0; i < 8; i++)
#pragma unroll
            for (int q = 0; q < 4; q++) sfr[i][q] = 0.f;

        const uint32_t kbase = sb + O_K + st * 16384;
#pragma unroll
        for (int ks = 0; ks < 8; ks++) {
#pragma unroll
            for (int jg = 0; jg < 4; jg++) {
                uint32_t bfr[4];
                int nrow = jg * 16 + (lj >> 1) * 8 + lr;
                int gg = 2 * ks + (lj & 1);
                ldmx4(bfr, kbase + nrow * 256 + swz16(nrow, gg) * 16);
                uint32_t b0[2] = { bfr[0], bfr[1] };
                uint32_t b1[2] = { bfr[2], bfr[3] };
                mma_tf32(sfr[jg * 2 + 0], qf[ks], b0);
                mma_tf32(sfr[jg * 2 + 1], qf[ks], b1);
            }
        }

        // --- softmax + causal mask + stage tf32-rounded P ---
        const bool need_mask = (jb >= 2 * qb);
#pragma unroll
        for (int jt = 0; jt < 8; jt++) {
            float p0 = fexp2(sfr[jt][0]);
            float p1 = fexp2(sfr[jt][1]);
            float p2 = fexp2(sfr[jt][2]);
            float p3 = fexp2(sfr[jt][3]);
            if (need_mask) {
                int j0 = jb * AKV + jt * 8 + qtid * 2;
                p0 = (j0     <= qrow_lo)     ? p0 : 0.f;
                p1 = (j0 + 1 <= qrow_lo)     ? p1 : 0.f;
                p2 = (j0     <= qrow_lo + 8) ? p2 : 0.f;
                p3 = (j0 + 1 <= qrow_lo + 8) ? p3 : 0.f;
            }
            l_lo += p0 + p1;
            l_hi += p2 + p3;
            int jl = jt * 8 + qtid * 2;
            int gg = jl >> 2, off = jl & 3;
            *reinterpret_cast<float2*>(
                smem + (pwarp - sb) + grp * 256 + swz16(grp, gg) * 16 + off * 4) =
                make_float2(ftf(p0), ftf(p1));
            *reinterpret_cast<float2*>(
                smem + (pwarp - sb) + (grp + 8) * 256 + swz16(grp + 8, gg) * 16 + off * 4) =
                make_float2(ftf(p2), ftf(p3));
        }

        __syncthreads();   // Vt + all P staged; K stage consumed
        if (jb + 2 < nkb) load_kv(jb + 2);
        CP_ASYNC_COMMIT();

        // --- O += P @ V ---
        const uint32_t vtbase = sb + O_VT;
#pragma unroll
        for (int ks = 0; ks < 8; ks++) {
            uint32_t a[4];
            {
                int row = (lj & 1) * 8 + lr;
                int gg = 2 * ks + (lj >> 1);
                ldmx4(a, pwarp + row * 256 + swz16(row, gg) * 16);
            }
#pragma unroll
            for (int jg = 0; jg < 4; jg++) {
                uint32_t bfr[4];
                int nrow = jg * 16 + (lj >> 1) * 8 + lr;
                int gg = 2 * ks + (lj & 1);
                ldmx4(bfr, vtbase + nrow * 256 + swz16(nrow, gg) * 16);
                uint32_t b0[2] = { bfr[0], bfr[1] };
                uint32_t b1[2] = { bfr[2], bfr[3] };
                mma_tf32(ofr[jg * 2 + 0], a, b0);
                mma_tf32(ofr[jg * 2 + 1], a, b1);
            }
        }
    }

    // --- finalize ---
    l_lo += __shfl_xor_sync(0xFFFFFFFF, l_lo, 1);
    l_lo += __shfl_xor_sync(0xFFFFFFFF, l_lo, 2);
    l_hi += __shfl_xor_sync(0xFFFFFFFF, l_hi, 1);
    l_hi += __shfl_xor_sync(0xFFFFFFFF, l_hi, 2);
    const float inv_lo = 1.f / l_lo, inv_hi = 1.f / l_hi;

    const int q_lo = qb * AQ + wq * 16 + grp;
#pragma unroll
    for (int jt = 0; jt < 8; jt++) {
        int d = jt * 8 + qtid * 2;
        float* base_lo = g_att + ((size_t)(b * Tz + q_lo) * Dz) + h * HDz + d;
        float* base_hi = base_lo + (size_t)8 * Dz;
        *reinterpret_cast<float2*>(base_lo) =
            make_float2(ftf(ofr[jt][0] * inv_lo), ftf(ofr[jt][1] * inv_lo));
        *reinterpret_cast<float2*>(base_hi) =
            make_float2(ftf(ofr[jt][2] * inv_hi), ftf(ofr[jt][3] * inv_hi));
    }
}

// ----------------------------------------------------------------------------
// Launch. Inputs: x, mask(unused), Wq, bq, Wk, Wv, bv, Wo, bo.
// ----------------------------------------------------------------------------
extern "C" void kernel_launch(void* const* d_in, const int* in_sizes, int n_in,
                              void* d_out, int out_size)
{
    const float* x  = (const float*)d_in[0];
    const float* Wq = (const float*)d_in[2];
    const float* bq = (const float*)d_in[3];
    const float* Wk = (const float*)d_in[4];
    const float* Wv = (const float*)d_in[5];
    const float* bv = (const float*)d_in[6];
    const float* Wo = (const float*)d_in[7];
    const float* bo = (const float*)d_in[8];
    float* out = (float*)d_out;

    float *p_q, *p_k, *p_v, *p_att;
    cudaGetSymbolAddress((void**)&p_q,   g_q);
    cudaGetSymbolAddress((void**)&p_k,   g_k);
    cudaGetSymbolAddress((void**)&p_v,   g_v);
    cudaGetSymbolAddress((void**)&p_att, g_att);

    cudaFuncSetAttribute(qkv_gemm_kernel,
                         cudaFuncAttributeMaxDynamicSharedMemorySize, GSMEM);
    cudaFuncSetAttribute(out_gemm_kernel,
                         cudaFuncAttributeMaxDynamicSharedMemorySize, GSMEM);
    cudaFuncSetAttribute(attn_kernel,
                         cudaFuncAttributeMaxDynamicSharedMemorySize, ASMEM);

    preround_kernel<<<(NPR + 255) / 256, 256>>>(
        (const float4*)x, (const float4*)Wq, (const float4*)Wk,
        (const float4*)Wv, (const float4*)Wo);

    qkv_gemm_kernel<<<dim3(Dz / GTN, Mz / 128, 3), 256, GSMEM>>>(
        bq, bv, p_q, p_k, p_v);

    attn_kernel<<<dim3(Tz / AQ, Hz, Bz), 256, ASMEM>>>();

    out_gemm_kernel<<<dim3(Dz / GTN, Mz / 128), 256, GSMEM>>>(p_att, bo, out);
}

// round 8
// speedup vs baseline: 4.7008x; 1.0245x over previous
#include <cuda_runtime.h>
#include <cstdint>

// ============================================================================
// MultiHeadAttention: B=8, T=1024, D=1024, H=16, hd=64, fp32.
// R8: attention softmax exp moved from FFMA polynomial to MUFU ex2.approx
// (FMA pipe was the binding resource); redundant per-chunk barrier removed
// from the 3-stage GEMM pipeline. Everything else unchanged from R7.
// ============================================================================

namespace {
constexpr int Bz = 8, Tz = 1024, Dz = 1024, Hz = 16, HDz = 64;
constexpr int Mz = Bz * Tz;  // 8192 rows
// 64^(-1/4) * sqrt(log2(e)): scores come out of QK^T already in log2 domain.
constexpr float SCALE_QK = 0.35355339059327373f * 1.2011224087864498f;
}

__device__ float g_q[(size_t)Mz * Dz];
__device__ float g_k[(size_t)Mz * Dz];
__device__ float g_v[(size_t)Mz * Dz];
__device__ float g_att[(size_t)Mz * Dz];
__device__ float g_xr[(size_t)Mz * Dz];        // tf32-rounded x
__device__ float g_wr[4][(size_t)Dz * Dz];     // tf32-rounded Wq, Wk, Wv, Wo

// ---------------------------------------------------------------------------
// PTX helpers
// ---------------------------------------------------------------------------
__device__ __forceinline__ uint32_t smem_u32(const void* p) {
    uint32_t a;
    asm("{ .reg .u64 t; cvta.to.shared.u64 t, %1; cvt.u32.u64 %0, t; }"
        : "=r"(a) : "l"(p));
    return a;
}
#define CP_ASYNC16(dst, src) \
    asm volatile("cp.async.cg.shared.global [%0], [%1], 16;" :: "r"(dst), "l"(src) : "memory")
#define CP_ASYNC_COMMIT() asm volatile("cp.async.commit_group;" ::: "memory")
#define CP_ASYNC_WAIT1()  asm volatile("cp.async.wait_group 1;" ::: "memory")
#define CP_ASYNC_WAIT0()  asm volatile("cp.async.wait_group 0;" ::: "memory")

__device__ __forceinline__ void ldmx4(uint32_t* r, uint32_t addr) {
    asm volatile("ldmatrix.sync.aligned.m8n8.x4.shared.b16 {%0, %1, %2, %3}, [%4];"
                 : "=r"(r[0]), "=r"(r[1]), "=r"(r[2]), "=r"(r[3]) : "r"(addr));
}
__device__ __forceinline__ uint32_t f2tf32(uint32_t x) {
    uint32_t o;
    asm("cvt.rna.tf32.f32 %0, %1;" : "=r"(o) : "f"(__uint_as_float(x)));
    return o;
}
__device__ __forceinline__ float ftf(float x) {
    return __uint_as_float(f2tf32(__float_as_uint(x)));
}
__device__ __forceinline__ void mma_tf32(float* c, const uint32_t* a, const uint32_t* b) {
    asm volatile(
        "mma.sync.aligned.m16n8k8.row.col.f32.tf32.tf32.f32 "
        "{%0, %1, %2, %3}, {%4, %5, %6, %7}, {%8, %9}, {%0, %1, %2, %3};"
        : "+f"(c[0]), "+f"(c[1]), "+f"(c[2]), "+f"(c[3])
        : "r"(a[0]), "r"(a[1]), "r"(a[2]), "r"(a[3]), "r"(b[0]), "r"(b[1]));
}

// MUFU 2^y (y already in log2 domain). SFU pipe; ~1-ulp class accuracy.
__device__ __forceinline__ float fexp2(float y) {
    float r;
    asm("ex2.approx.f32 %0, %1;" : "=f"(r) : "f"(y));
    return r;
}

// ---------------------------------------------------------------------------
// Pre-round: x and the 4 weight matrices -> tf32(rna) copies.
// ---------------------------------------------------------------------------
constexpr int NX4 = Mz * Dz / 4;
constexpr int NW4 = Dz * Dz / 4;
constexpr int NPR = NX4 + 4 * NW4;

__global__ __launch_bounds__(256) void preround_kernel(
    const float4* __restrict__ x,
    const float4* __restrict__ Wq, const float4* __restrict__ Wk,
    const float4* __restrict__ Wv, const float4* __restrict__ Wo)
{
    int i = blockIdx.x * blockDim.x + threadIdx.x;
    if (i >= NPR) return;
    const float4* src;
    float4* dst;
    if (i < NX4) {
        src = x + i;
        dst = reinterpret_cast<float4*>(g_xr) + i;
    } else {
        int j = i - NX4;
        int w = j / NW4, o = j % NW4;
        const float4* ws[4] = { Wq, Wk, Wv, Wo };
        src = ws[w] + o;
        dst = reinterpret_cast<float4*>(g_wr[w]) + o;
    }
    float4 v = *src;
    v.x = ftf(v.x); v.y = ftf(v.y); v.z = ftf(v.z); v.w = ftf(v.w);
    *dst = v;
}

// ---------------------------------------------------------------------------
// tf32 mma.sync GEMM body: C = alpha*(A @ W^T + bias). Pre-rounded operands;
// 128x128 tile, K-chunk 32, 3 stages, ONE barrier per chunk (3-stage safety:
// the top barrier orders compute(c-1) completion before issue(c+2)).
// ---------------------------------------------------------------------------
constexpr int GTN = 128, GCK = 32;
constexpr int GSTAGES = 3;
constexpr int NCHUNK = Dz / GCK;
constexpr int TILE_BYTES = 128 * GCK * 4;
constexpr int STAGE_BYTES = 2 * TILE_BYTES;
constexpr int GSMEM = STAGE_BYTES * GSTAGES;

__device__ __forceinline__ void gemm_body(
    const float* __restrict__ A, const float* __restrict__ W,
    const float* __restrict__ bias, float* __restrict__ C,
    float alpha, bool round_out, char* smem)
{
    const uint32_t sbase = smem_u32(smem);
    const int K = Dz, N = Dz;

    const int tid = threadIdx.x;
    const int wid = tid >> 5, lane = tid & 31;
    const int bn = blockIdx.x * GTN;
    const int bm = blockIdx.y * 128;
    const int wm = (wid & 3) * 32;
    const int wn = (wid >> 2) * 64;

    float acc[2][8][4];
#pragma unroll
    for (int i = 0; i < 2; i++)
#pragma unroll
        for (int j = 0; j < 8; j++)
#pragma unroll
            for (int q = 0; q < 4; q++) acc[i][j][q] = 0.f;

    auto issue_chunk = [&](int chunk) {
        const int k0 = chunk * GCK;
        const uint32_t st = sbase + (chunk % GSTAGES) * STAGE_BYTES;
#pragma unroll
        for (int p = 0; p < 8; p++) {
            int u = p * 256 + tid;
            if (u < 1024) {
                int r = u >> 3, c = u & 7;
                const float* src = A + (size_t)(bm + r) * K + k0 + c * 4;
                uint32_t dst = st + (uint32_t)(r * 128 + ((c ^ (r & 7)) << 4));
                CP_ASYNC16(dst, src);
            } else {
                int v = u - 1024;
                int r = v >> 3, c = v & 7;
                const float* src = W + (size_t)(bn + r) * K + k0 + c * 4;
                uint32_t dst = st + TILE_BYTES + (uint32_t)(r * 128 + ((c ^ (r & 7)) << 4));
                CP_ASYNC16(dst, src);
            }
        }
        CP_ASYNC_COMMIT();
    };

    issue_chunk(0);
    issue_chunk(1);

    const int lj = lane >> 3;
    const int lr = lane & 7;

    for (int chunk = 0; chunk < NCHUNK; chunk++) {
        CP_ASYNC_WAIT1();
        __syncthreads();   // chunk data visible; all warps past compute(c-1)
        if (chunk + 2 < NCHUNK) issue_chunk(chunk + 2);

        const uint32_t st = sbase + (chunk % GSTAGES) * STAGE_BYTES;
        const uint32_t sA = st, sB = st + TILE_BYTES;

#pragma unroll
        for (int ks = 0; ks < 4; ks++) {
            const int g = 2 * ks;
            uint32_t a[2][4];
#pragma unroll
            for (int i = 0; i < 2; i++) {
                int mrow = wm + i * 16 + (lj & 1) * 8 + lr;
                int gcol = g + (lj >> 1);
                uint32_t addr = sA + (uint32_t)(mrow * 128 + ((gcol ^ (mrow & 7)) << 4));
                ldmx4(a[i], addr);
            }
            uint32_t b[4][4];
#pragma unroll
            for (int jg = 0; jg < 4; jg++) {
                int nrow = wn + jg * 16 + (lj >> 1) * 8 + lr;
                int gcol = g + (lj & 1);
                uint32_t addr = sB + (uint32_t)(nrow * 128 + ((gcol ^ (nrow & 7)) << 4));
                ldmx4(b[jg], addr);
            }
#pragma unroll
            for (int i = 0; i < 2; i++)
#pragma unroll
                for (int jt = 0; jt < 8; jt++) {
                    uint32_t bp[2] = { b[jt >> 1][(jt & 1) * 2 + 0],
                                       b[jt >> 1][(jt & 1) * 2 + 1] };
                    mma_tf32(acc[i][jt], a[i], bp);
                }
        }
        // No trailing barrier: with 3 stages, the next iteration's top barrier
        // orders all warps' compute(c) before any issue into stage (c+3)%3.
    }
    CP_ASYNC_WAIT0();

    const int er = lane >> 2, ec = (lane & 3) * 2;
#pragma unroll
    for (int jt = 0; jt < 8; jt++) {
        int n = bn + wn + jt * 8 + ec;
        float2 bv = bias ? *reinterpret_cast<const float2*>(bias + n)
                         : make_float2(0.f, 0.f);
#pragma unroll
        for (int i = 0; i < 2; i++) {
            int m0 = bm + wm + i * 16 + er;
            float2 o0, o1;
            o0.x = alpha * (acc[i][jt][0] + bv.x);
            o0.y = alpha * (acc[i][jt][1] + bv.y);
            o1.x = alpha * (acc[i][jt][2] + bv.x);
            o1.y = alpha * (acc[i][jt][3] + bv.y);
            if (round_out) {
                o0.x = ftf(o0.x); o0.y = ftf(o0.y);
                o1.x = ftf(o1.x); o1.y = ftf(o1.y);
            }
            *reinterpret_cast<float2*>(C + (size_t)m0 * N + n) = o0;
            *reinterpret_cast<float2*>(C + (size_t)(m0 + 8) * N + n) = o1;
        }
    }
}

// Fused Q/K/V projections: blockIdx.z selects the GEMM (pre-rounded inputs).
__global__ __launch_bounds__(256) void qkv_gemm_kernel(
    const float* __restrict__ bq, const float* __restrict__ bv,
    float* __restrict__ pq, float* __restrict__ pk, float* __restrict__ pv)
{
    extern __shared__ __align__(1024) char smem[];
    if (blockIdx.z == 0)      gemm_body(g_xr, g_wr[0], bq,      pq, SCALE_QK, true, smem);
    else if (blockIdx.z == 1) gemm_body(g_xr, g_wr[1], nullptr, pk, SCALE_QK, true, smem);
    else                      gemm_body(g_xr, g_wr[2], bv,      pv, 1.0f,     true, smem);
}

__global__ __launch_bounds__(256) void out_gemm_kernel(
    const float* __restrict__ att, const float* __restrict__ bo,
    float* __restrict__ out)
{
    extern __shared__ __align__(1024) char smem[];
    gemm_body(att, g_wr[3], bo, out, 1.0f, false, smem);
}

// ---------------------------------------------------------------------------
// Tensor-core causal flash attention (R6 structure; exp on MUFU).
// ---------------------------------------------------------------------------
constexpr int AQ = 128, AKV = 64;
constexpr int O_Q  = 0;        // 32 KB: Q during prologue, then P staging
constexpr int O_K  = 32768;    // 2 x 16 KB
constexpr int O_VR = 65536;    // 2 x 16 KB (untransposed V stages)
constexpr int O_VT = 98304;    // 16 KB (V^T, [d][j])
constexpr int ASMEM = 114688 + 1024;

__device__ __forceinline__ uint32_t swz16(int row, int gg) {
    return (uint32_t)((gg & 8) | ((gg & 7) ^ (row & 7)));
}

__global__ __launch_bounds__(256, 1) void attn_kernel()
{
    const int qb = (int)gridDim.x - 1 - (int)blockIdx.x;  // heavy CTAs first
    const int h = blockIdx.y, b = blockIdx.z;

    extern __shared__ char smem_raw[];
    const uint32_t raw = smem_u32(smem_raw);
    const uint32_t sb = (raw + 1023u) & ~1023u;
    char* smem = smem_raw + (sb - raw);

    const int tid = threadIdx.x, lane = tid & 31, wq = tid >> 5;
    const int grp = lane >> 2, qtid = lane & 3;
    const int lj = lane >> 3, lr = lane & 7;

    const float* Qg = g_q + ((size_t)(b * Tz + qb * AQ)) * Dz + h * HDz;
    const float* Kg = g_k + ((size_t)b * Tz) * Dz + h * HDz;
    const float* Vg = g_v + ((size_t)b * Tz) * Dz + h * HDz;

    const int nkb = 2 * qb + 2;

    auto load_kv = [&](int jb) {
        const int st = jb & 1;
        const float* kp = Kg + (size_t)(jb * AKV) * Dz;
        const float* vp = Vg + (size_t)(jb * AKV) * Dz;
#pragma unroll
        for (int p = 0; p < 4; p++) {
            int idx = p * 256 + tid;
            int r = idx >> 4, gg = idx & 15;
            CP_ASYNC16(sb + O_K + st * 16384 + r * 256 + swz16(r, gg) * 16,
                       kp + (size_t)r * Dz + gg * 4);
            CP_ASYNC16(sb + O_VR + st * 16384 + r * 256 + gg * 16,
                       vp + (size_t)r * Dz + gg * 4);
        }
    };

    // Prologue: Q (group 0 with kv0), kv1 in group 1.
#pragma unroll
    for (int p = 0; p < 8; p++) {
        int idx = p * 256 + tid;
        int r = idx >> 4, gg = idx & 15;
        CP_ASYNC16(sb + O_Q + r * 256 + swz16(r, gg) * 16,
                   Qg + (size_t)r * Dz + gg * 4);
    }
    load_kv(0);
    CP_ASYNC_COMMIT();
    load_kv(1);
    CP_ASYNC_COMMIT();

    uint32_t qf[8][4];   // Q fragments, loaded once at jb==0
    float ofr[8][4];
#pragma unroll
    for (int i = 0; i < 8; i++)
#pragma unroll
        for (int q = 0; q < 4; q++) ofr[i][q] = 0.f;
    float l_lo = 0.f, l_hi = 0.f;

    const int qrow_lo = qb * AQ + wq * 16 + grp;
    const uint32_t pwarp = sb + O_Q + wq * 4096;   // P staging = old Q slice

    for (int jb = 0; jb < nkb; jb++) {
        const int st = jb & 1;
        CP_ASYNC_WAIT1();
        __syncthreads();

        if (jb == 0) {
            const uint32_t qbase = sb + O_Q + (wq * 16) * 256;
#pragma unroll
            for (int ks = 0; ks < 8; ks++) {
                int row = (lj & 1) * 8 + lr;
                int gg = 2 * ks + (lj >> 1);
                ldmx4(qf[ks], qbase + row * 256 + swz16(row, gg) * 16);
            }
        }

        // --- transpose V stage -> Vt[d][j] ---
        {
            const float4* vr = reinterpret_cast<const float4*>(smem + O_VR + st * 16384);
            float* vt = reinterpret_cast<float*>(smem + O_VT);
#pragma unroll
            for (int p = 0; p < 4; p++) {
                int idx = p * 256 + tid;
                int j = idx >> 4, gg = idx & 15;
                float4 v = vr[idx];
                int d0 = gg * 4;
                vt[(d0 + 0) * 64 + swz16(d0 + 0, j >> 2) * 4 + (j & 3)] = v.x;
                vt[(d0 + 1) * 64 + swz16(d0 + 1, j >> 2) * 4 + (j & 3)] = v.y;
                vt[(d0 + 2) * 64 + swz16(d0 + 2, j >> 2) * 4 + (j & 3)] = v.z;
                vt[(d0 + 3) * 64 + swz16(d0 + 3, j >> 2) * 4 + (j & 3)] = v.w;
            }
        }

        // --- S = Q @ K^T ---
        float sfr[8][4];
#pragma unroll
        for (int i = 0; i < 8; i++)
#pragma unroll
            for (int q = 0; q < 4; q++) sfr[i][q] = 0.f;

        const uint32_t kbase = sb + O_K + st * 16384;
#pragma unroll
        for (int ks = 0; ks < 8; ks++) {
#pragma unroll
            for (int jg = 0; jg < 4; jg++) {
                uint32_t bfr[4];
                int nrow = jg * 16 + (lj >> 1) * 8 + lr;
                int gg = 2 * ks + (lj & 1);
                ldmx4(bfr, kbase + nrow * 256 + swz16(nrow, gg) * 16);
                uint32_t b0[2] = { bfr[0], bfr[1] };
                uint32_t b1[2] = { bfr[2], bfr[3] };
                mma_tf32(sfr[jg * 2 + 0], qf[ks], b0);
                mma_tf32(sfr[jg * 2 + 1], qf[ks], b1);
            }
        }

        // --- softmax (MUFU exp2; scores in log2 domain) + mask + stage P ---
        const bool need_mask = (jb >= 2 * qb);
#pragma unroll
        for (int jt = 0; jt < 8; jt++) {
            float p0 = fexp2(sfr[jt][0]);
            float p1 = fexp2(sfr[jt][1]);
            float p2 = fexp2(sfr[jt][2]);
            float p3 = fexp2(sfr[jt][3]);
            if (need_mask) {
                int j0 = jb * AKV + jt * 8 + qtid * 2;
                p0 = (j0     <= qrow_lo)     ? p0 : 0.f;
                p1 = (j0 + 1 <= qrow_lo)     ? p1 : 0.f;
                p2 = (j0     <= qrow_lo + 8) ? p2 : 0.f;
                p3 = (j0 + 1 <= qrow_lo + 8) ? p3 : 0.f;
            }
            l_lo += p0 + p1;
            l_hi += p2 + p3;
            int jl = jt * 8 + qtid * 2;
            int gg = jl >> 2, off = jl & 3;
            *reinterpret_cast<float2*>(
                smem + (pwarp - sb) + grp * 256 + swz16(grp, gg) * 16 + off * 4) =
                make_float2(ftf(p0), ftf(p1));
            *reinterpret_cast<float2*>(
                smem + (pwarp - sb) + (grp + 8) * 256 + swz16(grp + 8, gg) * 16 + off * 4) =
                make_float2(ftf(p2), ftf(p3));
        }

        __syncthreads();   // Vt + all P staged; K stage consumed
        if (jb + 2 < nkb) load_kv(jb + 2);
        CP_ASYNC_COMMIT();

        // --- O += P @ V ---
        const uint32_t vtbase = sb + O_VT;
#pragma unroll
        for (int ks = 0; ks < 8; ks++) {
            uint32_t a[4];
            {
                int row = (lj & 1) * 8 + lr;
                int gg = 2 * ks + (lj >> 1);
                ldmx4(a, pwarp + row * 256 + swz16(row, gg) * 16);
            }
#pragma unroll
            for (int jg = 0; jg < 4; jg++) {
                uint32_t bfr[4];
                int nrow = jg * 16 + (lj >> 1) * 8 + lr;
                int gg = 2 * ks + (lj & 1);
                ldmx4(bfr, vtbase + nrow * 256 + swz16(nrow, gg) * 16);
                uint32_t b0[2] = { bfr[0], bfr[1] };
                uint32_t b1[2] = { bfr[2], bfr[3] };
                mma_tf32(ofr[jg * 2 + 0], a, b0);
                mma_tf32(ofr[jg * 2 + 1], a, b1);
            }
        }
    }

    // --- finalize ---
    l_lo += __shfl_xor_sync(0xFFFFFFFF, l_lo, 1);
    l_lo += __shfl_xor_sync(0xFFFFFFFF, l_lo, 2);
    l_hi += __shfl_xor_sync(0xFFFFFFFF, l_hi, 1);
    l_hi += __shfl_xor_sync(0xFFFFFFFF, l_hi, 2);
    const float inv_lo = 1.f / l_lo, inv_hi = 1.f / l_hi;

    const int q_lo = qb * AQ + wq * 16 + grp;
#pragma unroll
    for (int jt = 0; jt < 8; jt++) {
        int d = jt * 8 + qtid * 2;
        float* base_lo = g_att + ((size_t)(b * Tz + q_lo) * Dz) + h * HDz + d;
        float* base_hi = base_lo + (size_t)8 * Dz;
        *reinterpret_cast<float2*>(base_lo) =
            make_float2(ftf(ofr[jt][0] * inv_lo), ftf(ofr[jt][1] * inv_lo));
        *reinterpret_cast<float2*>(base_hi) =
            make_float2(ftf(ofr[jt][2] * inv_hi), ftf(ofr[jt][3] * inv_hi));
    }
}

// ----------------------------------------------------------------------------
// Launch. Inputs: x, mask(unused), Wq, bq, Wk, Wv, bv, Wo, bo.
// ----------------------------------------------------------------------------
extern "C" void kernel_launch(void* const* d_in, const int* in_sizes, int n_in,
                              void* d_out, int out_size)
{
    const float* x  = (const float*)d_in[0];
    const float* Wq = (const float*)d_in[2];
    const float* bq = (const float*)d_in[3];
    const float* Wk = (const float*)d_in[4];
    const float* Wv = (const float*)d_in[5];
    const float* bv = (const float*)d_in[6];
    const float* Wo = (const float*)d_in[7];
    const float* bo = (const float*)d_in[8];
    float* out = (float*)d_out;

    float *p_q, *p_k, *p_v, *p_att;
    cudaGetSymbolAddress((void**)&p_q,   g_q);
    cudaGetSymbolAddress((void**)&p_k,   g_k);
    cudaGetSymbolAddress((void**)&p_v,   g_v);
    cudaGetSymbolAddress((void**)&p_att, g_att);

    cudaFuncSetAttribute(qkv_gemm_kernel,
                         cudaFuncAttributeMaxDynamicSharedMemorySize, GSMEM);
    cudaFuncSetAttribute(out_gemm_kernel,
                         cudaFuncAttributeMaxDynamicSharedMemorySize, GSMEM);
    cudaFuncSetAttribute(attn_kernel,
                         cudaFuncAttributeMaxDynamicSharedMemorySize, ASMEM);

    preround_kernel<<<(NPR + 255) / 256, 256>>>(
        (const float4*)x, (const float4*)Wq, (const float4*)Wk,
        (const float4*)Wv, (const float4*)Wo);

    qkv_gemm_kernel<<<dim3(Dz / GTN, Mz / 128, 3), 256, GSMEM>>>(
        bq, bv, p_q, p_k, p_v);

    attn_kernel<<<dim3(Tz / AQ, Hz, Bz), 256, ASMEM>>>();

    out_gemm_kernel<<<dim3(Dz / GTN, Mz / 128), 256, GSMEM>>>(p_att, bo, out);
}